// round 3
// baseline (speedup 1.0000x reference)
#include <cuda_runtime.h>
#include <mma.h>
#include <math.h>

using namespace nvcuda;

#define BATCH 2
#define SEQ   2048
#define DM    1024
#define NH    16
#define DEPTH 64
#define MROWS (BATCH * SEQ)       // 4096
#define NROWS (BATCH * NH * SEQ)  // 65536 attention rows
#define JT    (SEQ / 128)         // 16 j-tiles per row

// Scratch (allocation-free rule: __device__ globals)
__device__ float g_q[BATCH * SEQ * DM];
__device__ float g_k[BATCH * SEQ * DM];
__device__ float g_v[BATCH * SEQ * DM];
__device__ float g_ctx[BATCH * SEQ * DM];
__device__ float g_partial[JT * NROWS];   // per-(jtile,row) exp partial sums
__device__ float g_rowinv[NROWS];         // 1 / row sum

template <class Frag>
__device__ __forceinline__ void frag_to_tf32(Frag& f) {
    #pragma unroll
    for (int i = 0; i < f.num_elements; ++i)
        f.x[i] = wmma::__float_to_tf32(f.x[i]);
}

// ---------------------------------------------------------------------------
// TF32 GEMM + bias: C[M,N] = A[M,K] @ W[K,N] + bias[N]
// Block 128x128, BK=32, 512 threads = 16 warps (4m x 4n), warp tile 32x32.
// ---------------------------------------------------------------------------
__global__ __launch_bounds__(512)
void proj_gemm_tf32(const float* __restrict__ A, const float* __restrict__ W,
                    const float* __restrict__ bias, float* __restrict__ C,
                    int M, int N, int K)
{
    __shared__ float As[128][36];    // [m][k]
    __shared__ float Bs[32][132];    // [k][n]
    __shared__ float BiasS[16][132];

    const int tid  = threadIdx.x;
    const int wid  = tid >> 5;
    const int brow = blockIdx.y * 128;
    const int bcol = blockIdx.x * 128;
    const int wm   = (wid >> 2) * 32;
    const int wn   = (wid & 3) * 32;

    #pragma unroll
    for (int p = 0; p < 4; ++p) {
        const int f = tid + p * 512;   // 0..2047
        BiasS[f >> 7][f & 127] = bias[bcol + (f & 127)];
    }
    __syncthreads();

    wmma::fragment<wmma::accumulator, 16, 16, 8, float> acc[2][2];
    #pragma unroll
    for (int i = 0; i < 2; ++i)
        #pragma unroll
        for (int j = 0; j < 2; ++j)
            wmma::load_matrix_sync(acc[i][j], &BiasS[0][wn + j * 16], 132,
                                   wmma::mem_row_major);

    const int aR = tid >> 3;            // 0..63
    const int aC = (tid & 7) << 2;      // 0..28
    const int bR = tid >> 5;            // 0..15
    const int bC = (tid & 31) << 2;     // 0..124

    for (int k0 = 0; k0 < K; k0 += 32) {
        #pragma unroll
        for (int p = 0; p < 2; ++p) {
            const int r = aR + p * 64;
            *(float4*)&As[r][aC] =
                *(const float4*)(A + (size_t)(brow + r) * K + k0 + aC);
        }
        #pragma unroll
        for (int p = 0; p < 2; ++p) {
            const int r = bR + p * 16;
            *(float4*)&Bs[r][bC] =
                *(const float4*)(W + (size_t)(k0 + r) * N + bcol + bC);
        }
        __syncthreads();

        #pragma unroll
        for (int kk = 0; kk < 32; kk += 8) {
            wmma::fragment<wmma::matrix_a, 16, 16, 8, wmma::precision::tf32,
                           wmma::row_major> af[2];
            wmma::fragment<wmma::matrix_b, 16, 16, 8, wmma::precision::tf32,
                           wmma::row_major> bf[2];
            #pragma unroll
            for (int i = 0; i < 2; ++i) {
                wmma::load_matrix_sync(af[i], &As[wm + i * 16][kk], 36);
                frag_to_tf32(af[i]);
            }
            #pragma unroll
            for (int j = 0; j < 2; ++j) {
                wmma::load_matrix_sync(bf[j], &Bs[kk][wn + j * 16], 132);
                frag_to_tf32(bf[j]);
            }
            #pragma unroll
            for (int i = 0; i < 2; ++i)
                #pragma unroll
                for (int j = 0; j < 2; ++j)
                    wmma::mma_sync(acc[i][j], af[i], bf[j], acc[i][j]);
        }
        __syncthreads();
    }

    #pragma unroll
    for (int i = 0; i < 2; ++i)
        #pragma unroll
        for (int j = 0; j < 2; ++j)
            wmma::store_matrix_sync(
                C + (size_t)(brow + wm + i * 16) * N + bcol + wn + j * 16,
                acc[i][j], N, wmma::mem_row_major);
}

// ---------------------------------------------------------------------------
// Scores + exp (TF32): attn[bh,i,j] = exp(scale * Q.K^T), unnormalized.
// Also writes deterministic per-(jtile,row) partial exp sums.
// Block 128i x 128j, 512 threads, 16 warps (4x4), warp 32x32.
// Dynamic smem: Qs/Ks tiles (36KB) reused as exp tile (67.6KB) for row sums.
// ---------------------------------------------------------------------------
__global__ __launch_bounds__(512)
void scores_exp_tf32(const float* __restrict__ q, const float* __restrict__ k,
                     float* __restrict__ attn, float* __restrict__ partial)
{
    extern __shared__ float sm[];
    float* Qs = sm;                 // [128][36]
    float* Ks = sm + 128 * 36;      // [128][36]
    float* Es = sm;                 // [128][132] (reuse after compute)

    const int bh = blockIdx.z;
    const int b  = bh >> 4;
    const int h  = bh & 15;
    const int i0 = blockIdx.y * 128;
    const int j0 = blockIdx.x * 128;
    const int tid = threadIdx.x;
    const int wid = tid >> 5;
    const int wm  = (wid >> 2) * 32;
    const int wn  = (wid & 3) * 32;

    const float* qbase = q + (size_t)b * SEQ * DM + h * DEPTH;
    const float* kbase = k + (size_t)b * SEQ * DM + h * DEPTH;

    wmma::fragment<wmma::accumulator, 16, 16, 8, float> acc[2][2];
    #pragma unroll
    for (int i = 0; i < 2; ++i)
        #pragma unroll
        for (int j = 0; j < 2; ++j)
            wmma::fill_fragment(acc[i][j], 0.0f);

    const int lR = tid >> 3;            // 0..63
    const int lC = (tid & 7) << 2;      // 0..28

    #pragma unroll
    for (int d0 = 0; d0 < DEPTH; d0 += 32) {
        #pragma unroll
        for (int p = 0; p < 2; ++p) {
            const int r = lR + p * 64;
            *(float4*)&Qs[r * 36 + lC] =
                *(const float4*)(qbase + (size_t)(i0 + r) * DM + d0 + lC);
            *(float4*)&Ks[r * 36 + lC] =
                *(const float4*)(kbase + (size_t)(j0 + r) * DM + d0 + lC);
        }
        __syncthreads();

        #pragma unroll
        for (int kk = 0; kk < 32; kk += 8) {
            wmma::fragment<wmma::matrix_a, 16, 16, 8, wmma::precision::tf32,
                           wmma::row_major> af[2];
            wmma::fragment<wmma::matrix_b, 16, 16, 8, wmma::precision::tf32,
                           wmma::col_major> bf[2];
            #pragma unroll
            for (int i = 0; i < 2; ++i) {
                wmma::load_matrix_sync(af[i], &Qs[(wm + i * 16) * 36 + kk], 36);
                frag_to_tf32(af[i]);
            }
            #pragma unroll
            for (int j = 0; j < 2; ++j) {
                wmma::load_matrix_sync(bf[j], &Ks[(wn + j * 16) * 36 + kk], 36);
                frag_to_tf32(bf[j]);
            }
            #pragma unroll
            for (int i = 0; i < 2; ++i)
                #pragma unroll
                for (int j = 0; j < 2; ++j)
                    wmma::mma_sync(acc[i][j], af[i], bf[j], acc[i][j]);
        }
        __syncthreads();
    }

    // exp(scale * s) on fragment registers
    const float scale = 0.125f;   // 1/sqrt(64)
    #pragma unroll
    for (int i = 0; i < 2; ++i)
        #pragma unroll
        for (int j = 0; j < 2; ++j)
            #pragma unroll
            for (int e = 0; e < acc[i][j].num_elements; ++e)
                acc[i][j].x[e] = __expf(acc[i][j].x[e] * scale);

    // Store unnormalized exp to gmem (attn buffer) and to smem for row sums
    float* obase = attn + (size_t)bh * SEQ * SEQ;
    #pragma unroll
    for (int i = 0; i < 2; ++i)
        #pragma unroll
        for (int j = 0; j < 2; ++j) {
            wmma::store_matrix_sync(
                obase + (size_t)(i0 + wm + i * 16) * SEQ + j0 + wn + j * 16,
                acc[i][j], SEQ, wmma::mem_row_major);
            wmma::store_matrix_sync(
                &Es[(wm + i * 16) * 132 + wn + j * 16],
                acc[i][j], 132, wmma::mem_row_major);
        }
    __syncthreads();

    // Row sums: 4 threads per row, 32 cols each (interleaved float4s)
    const int row = tid >> 2;       // 0..127
    const int prt = tid & 3;
    float s = 0.0f;
    #pragma unroll
    for (int j = 0; j < 8; ++j) {
        float4 v = *(float4*)&Es[row * 132 + prt * 4 + 16 * j];
        s += (v.x + v.y) + (v.z + v.w);
    }
    s += __shfl_xor_sync(0xffffffffu, s, 1);
    s += __shfl_xor_sync(0xffffffffu, s, 2);
    if (prt == 0)
        partial[(size_t)blockIdx.x * NROWS + (size_t)bh * SEQ + i0 + row] = s;
}

// ---------------------------------------------------------------------------
// Deterministic row-sum reduction -> reciprocal
// ---------------------------------------------------------------------------
__global__ __launch_bounds__(256)
void rowinv_kernel(const float* __restrict__ partial, float* __restrict__ rowinv)
{
    const int idx = blockIdx.x * 256 + threadIdx.x;
    float s = 0.0f;
    #pragma unroll
    for (int jt = 0; jt < JT; ++jt)
        s += partial[(size_t)jt * NROWS + idx];
    rowinv[idx] = 1.0f / s;
}

// ---------------------------------------------------------------------------
// Context (TF32) + attn normalization writeback:
//   attn[bh,m,k] = exp * rowinv[m]   (written back, final output)
//   ctx[b,m,h*64+d] = sum_k attn * v
// Block 128m x 64n, 256 threads, 8 warps (4m x 2n), warp 32x32, BK=32.
// ---------------------------------------------------------------------------
__global__ __launch_bounds__(256)
void ctx_norm_tf32(float* __restrict__ attn, const float* __restrict__ v,
                   const float* __restrict__ rowinv, float* __restrict__ ctx)
{
    __shared__ float As[128][36];   // [m][k] normalized attn
    __shared__ float Vs[32][72];    // [k][d]
    __shared__ float invs[128];

    const int bh = blockIdx.z;
    const int b  = bh >> 4;
    const int h  = bh & 15;
    const int m0 = blockIdx.y * 128;
    const int tid = threadIdx.x;
    const int wid = tid >> 5;
    const int wm  = (wid >> 1) * 32;
    const int wn  = (wid & 1) * 32;

    if (tid < 128)
        invs[tid] = rowinv[(size_t)bh * SEQ + m0 + tid];
    __syncthreads();

    float* abase = attn + (size_t)bh * SEQ * SEQ;
    const float* vbase = v + (size_t)b * SEQ * DM + h * DEPTH;

    wmma::fragment<wmma::accumulator, 16, 16, 8, float> acc[2][2];
    #pragma unroll
    for (int i = 0; i < 2; ++i)
        #pragma unroll
        for (int j = 0; j < 2; ++j)
            wmma::fill_fragment(acc[i][j], 0.0f);

    const int aR = tid >> 3;            // 0..31
    const int aC = (tid & 7) << 2;      // 0..28
    const int vR = tid >> 4;            // 0..15
    const int vC = (tid & 15) << 2;     // 0..60

    for (int k0 = 0; k0 < SEQ; k0 += 32) {
        #pragma unroll
        for (int p = 0; p < 4; ++p) {
            const int r = aR + p * 32;
            float* gp = abase + (size_t)(m0 + r) * SEQ + k0 + aC;
            float4 a = *(const float4*)gp;
            const float iv = invs[r];
            a.x *= iv; a.y *= iv; a.z *= iv; a.w *= iv;
            *(float4*)gp = a;                 // normalized attn (final output)
            *(float4*)&As[r][aC] = a;
        }
        #pragma unroll
        for (int p = 0; p < 2; ++p) {
            const int r = vR + p * 16;
            *(float4*)&Vs[r][vC] =
                *(const float4*)(vbase + (size_t)(k0 + r) * DM + vC);
        }
        __syncthreads();

        #pragma unroll
        for (int kk = 0; kk < 32; kk += 8) {
            wmma::fragment<wmma::matrix_a, 16, 16, 8, wmma::precision::tf32,
                           wmma::row_major> af[2];
            wmma::fragment<wmma::matrix_b, 16, 16, 8, wmma::precision::tf32,
                           wmma::row_major> bf[2];
            #pragma unroll
            for (int i = 0; i < 2; ++i) {
                wmma::load_matrix_sync(af[i], &As[wm + i * 16][kk], 36);
                frag_to_tf32(af[i]);
            }
            #pragma unroll
            for (int j = 0; j < 2; ++j) {
                wmma::load_matrix_sync(bf[j], &Vs[kk][wn + j * 16], 72);
                frag_to_tf32(bf[j]);
            }
            #pragma unroll
            for (int i = 0; i < 2; ++i)
                #pragma unroll
                for (int j = 0; j < 2; ++j)
                    wmma::mma_sync(acc[i][j], af[i], bf[j], acc[i][j]);
        }
        __syncthreads();
    }

    #pragma unroll
    for (int i = 0; i < 2; ++i)
        #pragma unroll
        for (int j = 0; j < 2; ++j)
            wmma::store_matrix_sync(
                ctx + (size_t)(b * SEQ + m0 + wm + i * 16) * DM
                    + h * DEPTH + wn + j * 16,
                acc[i][j], DM, wmma::mem_row_major);
}

// ---------------------------------------------------------------------------
extern "C" void kernel_launch(void* const* d_in, const int* in_sizes, int n_in,
                              void* d_out, int out_size)
{
    const float* query = (const float*)d_in[0];
    const float* key   = (const float*)d_in[1];
    const float* value = (const float*)d_in[2];
    const float* Wq = (const float*)d_in[3];
    const float* bq = (const float*)d_in[4];
    const float* Wk = (const float*)d_in[5];
    const float* bk = (const float*)d_in[6];
    const float* Wv = (const float*)d_in[7];
    const float* bv = (const float*)d_in[8];
    const float* Wo = (const float*)d_in[9];
    const float* bo = (const float*)d_in[10];

    float* out  = (float*)d_out;
    float* attn = out + (size_t)BATCH * SEQ * DM;

    float *q, *k, *v, *ctx, *partial, *rowinv;
    cudaGetSymbolAddress((void**)&q,       g_q);
    cudaGetSymbolAddress((void**)&k,       g_k);
    cudaGetSymbolAddress((void**)&v,       g_v);
    cudaGetSymbolAddress((void**)&ctx,     g_ctx);
    cudaGetSymbolAddress((void**)&partial, g_partial);
    cudaGetSymbolAddress((void**)&rowinv,  g_rowinv);

    static int smem_set = 0;
    if (!smem_set) {
        cudaFuncSetAttribute(scores_exp_tf32,
                             cudaFuncAttributeMaxDynamicSharedMemorySize,
                             128 * 132 * 4);
        smem_set = 1;
    }

    dim3 gproj(DM / 128, MROWS / 128);   // (8, 32)
    proj_gemm_tf32<<<gproj, 512>>>(query, Wq, bq, q, MROWS, DM, DM);
    proj_gemm_tf32<<<gproj, 512>>>(key,   Wk, bk, k, MROWS, DM, DM);
    proj_gemm_tf32<<<gproj, 512>>>(value, Wv, bv, v, MROWS, DM, DM);

    dim3 gsc(SEQ / 128, SEQ / 128, BATCH * NH);  // (16, 16, 32)
    scores_exp_tf32<<<gsc, 512, 128 * 132 * 4>>>(q, k, attn, partial);

    rowinv_kernel<<<NROWS / 256, 256>>>(partial, rowinv);

    dim3 gctx(1, SEQ / 128, BATCH * NH);         // (1, 16, 32)
    ctx_norm_tf32<<<gctx, 256>>>(attn, v, rowinv, ctx);

    proj_gemm_tf32<<<gproj, 512>>>(ctx, Wo, bo, out, MROWS, DM, DM);
}

// round 4
// speedup vs baseline: 1.0108x; 1.0108x over previous
#include <cuda_runtime.h>
#include <mma.h>
#include <math.h>

using namespace nvcuda;

#define BATCH 2
#define SEQ   2048
#define DM    1024
#define NH    16
#define DEPTH 64
#define MROWS (BATCH * SEQ)       // 4096
#define NROWS (BATCH * NH * SEQ)  // 65536 attention rows
#define JT    (SEQ / 128)         // 16 j-tiles per row

// Scratch (allocation-free rule: __device__ globals)
__device__ float g_q[BATCH * SEQ * DM];
__device__ float g_k[BATCH * SEQ * DM];
__device__ float g_v[BATCH * SEQ * DM];
__device__ float g_ctx[BATCH * SEQ * DM];
__device__ float g_partial[JT * NROWS];   // per-(jtile,row) exp partial sums
__device__ float g_rowinv[NROWS];         // 1 / row sum

template <class Frag>
__device__ __forceinline__ void frag_to_tf32(Frag& f) {
    #pragma unroll
    for (int i = 0; i < f.num_elements; ++i)
        f.x[i] = wmma::__float_to_tf32(f.x[i]);
}

// ---------------------------------------------------------------------------
// TF32 GEMM + bias: C[M,N] = A[M,K] @ W[K,N] + bias[N]
// Block tile 128x128, BK=32, 256 threads = 8 warps (4m x 2n), warp tile 32x64.
// (Exact R2 configuration — measured 57 TF/s.)
// ---------------------------------------------------------------------------
__global__ __launch_bounds__(256)
void proj_gemm_tf32(const float* __restrict__ A, const float* __restrict__ W,
                    const float* __restrict__ bias, float* __restrict__ C,
                    int M, int N, int K)
{
    __shared__ float As[128][36];    // [m][k]
    __shared__ float Bs[32][132];    // [k][n]
    __shared__ float BiasS[16][132];

    const int tid  = threadIdx.x;
    const int wid  = tid >> 5;
    const int brow = blockIdx.y * 128;
    const int bcol = blockIdx.x * 128;
    const int wm   = (wid >> 1) * 32;
    const int wn   = (wid & 1) * 64;

    #pragma unroll
    for (int p = 0; p < 8; ++p) {
        const int f = tid + p * 256;   // 0..2047
        BiasS[f >> 7][f & 127] = bias[bcol + (f & 127)];
    }
    __syncthreads();

    wmma::fragment<wmma::accumulator, 16, 16, 8, float> acc[2][4];
    #pragma unroll
    for (int i = 0; i < 2; ++i)
        #pragma unroll
        for (int j = 0; j < 4; ++j)
            wmma::load_matrix_sync(acc[i][j], &BiasS[0][wn + j * 16], 132,
                                   wmma::mem_row_major);

    const int aR = tid >> 3;            // 0..31
    const int aC = (tid & 7) << 2;      // 0..28
    const int bR = tid >> 5;            // 0..7
    const int bC = (tid & 31) << 2;     // 0..124

    for (int k0 = 0; k0 < K; k0 += 32) {
        #pragma unroll
        for (int p = 0; p < 4; ++p) {
            const int r = aR + p * 32;
            *(float4*)&As[r][aC] =
                *(const float4*)(A + (size_t)(brow + r) * K + k0 + aC);
        }
        #pragma unroll
        for (int p = 0; p < 4; ++p) {
            const int r = bR + p * 8;
            *(float4*)&Bs[r][bC] =
                *(const float4*)(W + (size_t)(k0 + r) * N + bcol + bC);
        }
        __syncthreads();

        #pragma unroll
        for (int kk = 0; kk < 32; kk += 8) {
            wmma::fragment<wmma::matrix_a, 16, 16, 8, wmma::precision::tf32,
                           wmma::row_major> af[2];
            wmma::fragment<wmma::matrix_b, 16, 16, 8, wmma::precision::tf32,
                           wmma::row_major> bf[4];
            #pragma unroll
            for (int i = 0; i < 2; ++i) {
                wmma::load_matrix_sync(af[i], &As[wm + i * 16][kk], 36);
                frag_to_tf32(af[i]);
            }
            #pragma unroll
            for (int j = 0; j < 4; ++j) {
                wmma::load_matrix_sync(bf[j], &Bs[kk][wn + j * 16], 132);
                frag_to_tf32(bf[j]);
            }
            #pragma unroll
            for (int i = 0; i < 2; ++i)
                #pragma unroll
                for (int j = 0; j < 4; ++j)
                    wmma::mma_sync(acc[i][j], af[i], bf[j], acc[i][j]);
        }
        __syncthreads();
    }

    #pragma unroll
    for (int i = 0; i < 2; ++i)
        #pragma unroll
        for (int j = 0; j < 4; ++j)
            wmma::store_matrix_sync(
                C + (size_t)(brow + wm + i * 16) * N + bcol + wn + j * 16,
                acc[i][j], N, wmma::mem_row_major);
}

// ---------------------------------------------------------------------------
// Scores + exp (TF32): attn[bh,i,j] = exp(scale * Q.K^T), unnormalized.
// Per-(jtile,row) partial sums via register-only fragment reduction:
// HMMA f32 accumulator layout: lane = 4g+t holds, per fragment,
//   e0,e1,e4,e5 -> row g ; e2,e3,e6,e7 -> row g+8.
// Block 128i x 128j, 256 threads, warp tile 32x64 (exact R2 main loop).
// ---------------------------------------------------------------------------
__global__ __launch_bounds__(256)
void scores_exp_tf32(const float* __restrict__ q, const float* __restrict__ k,
                     float* __restrict__ attn, float* __restrict__ partial)
{
    __shared__ float Qs[128][36];   // [i][d]
    __shared__ float Ks[128][36];   // [j][d]
    __shared__ float psum[128];

    const int bh = blockIdx.z;
    const int b  = bh >> 4;
    const int h  = bh & 15;
    const int i0 = blockIdx.y * 128;
    const int j0 = blockIdx.x * 128;
    const int tid  = threadIdx.x;
    const int lane = tid & 31;
    const int wid  = tid >> 5;
    const int wm   = (wid >> 1) * 32;
    const int wn   = (wid & 1) * 64;

    const float* qbase = q + (size_t)b * SEQ * DM + h * DEPTH;
    const float* kbase = k + (size_t)b * SEQ * DM + h * DEPTH;

    if (tid < 128) psum[tid] = 0.0f;

    wmma::fragment<wmma::accumulator, 16, 16, 8, float> acc[2][4];
    #pragma unroll
    for (int i = 0; i < 2; ++i)
        #pragma unroll
        for (int j = 0; j < 4; ++j)
            wmma::fill_fragment(acc[i][j], 0.0f);

    const int lR = tid >> 3;            // 0..31
    const int lC = (tid & 7) << 2;      // 0..28

    #pragma unroll
    for (int d0 = 0; d0 < DEPTH; d0 += 32) {
        #pragma unroll
        for (int p = 0; p < 4; ++p) {
            const int r = lR + p * 32;
            *(float4*)&Qs[r][lC] =
                *(const float4*)(qbase + (size_t)(i0 + r) * DM + d0 + lC);
            *(float4*)&Ks[r][lC] =
                *(const float4*)(kbase + (size_t)(j0 + r) * DM + d0 + lC);
        }
        __syncthreads();

        #pragma unroll
        for (int kk = 0; kk < 32; kk += 8) {
            wmma::fragment<wmma::matrix_a, 16, 16, 8, wmma::precision::tf32,
                           wmma::row_major> af[2];
            wmma::fragment<wmma::matrix_b, 16, 16, 8, wmma::precision::tf32,
                           wmma::col_major> bf[4];
            #pragma unroll
            for (int i = 0; i < 2; ++i) {
                wmma::load_matrix_sync(af[i], &Qs[wm + i * 16][kk], 36);
                frag_to_tf32(af[i]);
            }
            #pragma unroll
            for (int j = 0; j < 4; ++j) {
                wmma::load_matrix_sync(bf[j], &Ks[wn + j * 16][kk], 36);
                frag_to_tf32(bf[j]);
            }
            #pragma unroll
            for (int i = 0; i < 2; ++i)
                #pragma unroll
                for (int j = 0; j < 4; ++j)
                    wmma::mma_sync(acc[i][j], af[i], bf[j], acc[i][j]);
        }
        __syncthreads();
    }

    // exp(scale*s) + per-row partials from fragment registers
    const float scale = 0.125f;   // 1/sqrt(64)
    float* obase = attn + (size_t)bh * SEQ * SEQ;
    float lo[2] = {0.0f, 0.0f};   // row = wm + i*16 + g
    float hi[2] = {0.0f, 0.0f};   // row = wm + i*16 + 8 + g

    #pragma unroll
    for (int i = 0; i < 2; ++i) {
        #pragma unroll
        for (int j = 0; j < 4; ++j) {
            #pragma unroll
            for (int e = 0; e < 8; ++e) {
                const float x = __expf(acc[i][j].x[e] * scale);
                acc[i][j].x[e] = x;
                if ((e & 3) < 2) lo[i] += x; else hi[i] += x;
            }
            wmma::store_matrix_sync(
                obase + (size_t)(i0 + wm + i * 16) * SEQ + j0 + wn + j * 16,
                acc[i][j], SEQ, wmma::mem_row_major);
        }
        // reduce over the 4 lanes sharing a row (t = lane & 3)
        lo[i] += __shfl_xor_sync(0xffffffffu, lo[i], 1);
        lo[i] += __shfl_xor_sync(0xffffffffu, lo[i], 2);
        hi[i] += __shfl_xor_sync(0xffffffffu, hi[i], 1);
        hi[i] += __shfl_xor_sync(0xffffffffu, hi[i], 2);
    }

    __syncthreads();   // psum zeros visible
    if ((lane & 3) == 0) {
        const int g = lane >> 2;   // 0..7
        #pragma unroll
        for (int i = 0; i < 2; ++i) {
            atomicAdd(&psum[wm + i * 16 + g],     lo[i]);   // 2 commutative adds
            atomicAdd(&psum[wm + i * 16 + 8 + g], hi[i]);   // -> deterministic
        }
    }
    __syncthreads();
    if (tid < 128)
        partial[(size_t)blockIdx.x * NROWS + (size_t)bh * SEQ + i0 + tid] =
            psum[tid];
}

// ---------------------------------------------------------------------------
// Deterministic row-sum reduction -> reciprocal
// ---------------------------------------------------------------------------
__global__ __launch_bounds__(256)
void rowinv_kernel(const float* __restrict__ partial, float* __restrict__ rowinv)
{
    const int idx = blockIdx.x * 256 + threadIdx.x;
    float s = 0.0f;
    #pragma unroll
    for (int jt = 0; jt < JT; ++jt)
        s += partial[(size_t)jt * NROWS + idx];
    rowinv[idx] = 1.0f / s;
}

// ---------------------------------------------------------------------------
// Context (TF32) + attn normalization writeback:
//   attn[bh,m,k] = exp * rowinv[m]   (written back, final output)
//   ctx[b,m,h*64+d] = sum_k attn * v
// Block 128m x 64n, 256 threads, 8 warps (4m x 2n), warp 32x32, BK=32.
// ---------------------------------------------------------------------------
__global__ __launch_bounds__(256)
void ctx_norm_tf32(float* __restrict__ attn, const float* __restrict__ v,
                   const float* __restrict__ rowinv, float* __restrict__ ctx)
{
    __shared__ float As[128][36];   // [m][k] normalized attn
    __shared__ float Vs[32][72];    // [k][d]
    __shared__ float invs[128];

    const int bh = blockIdx.z;
    const int b  = bh >> 4;
    const int h  = bh & 15;
    const int m0 = blockIdx.y * 128;
    const int tid = threadIdx.x;
    const int wid = tid >> 5;
    const int wm  = (wid >> 1) * 32;
    const int wn  = (wid & 1) * 32;

    if (tid < 128)
        invs[tid] = rowinv[(size_t)bh * SEQ + m0 + tid];
    __syncthreads();

    float* abase = attn + (size_t)bh * SEQ * SEQ;
    const float* vbase = v + (size_t)b * SEQ * DM + h * DEPTH;

    wmma::fragment<wmma::accumulator, 16, 16, 8, float> acc[2][2];
    #pragma unroll
    for (int i = 0; i < 2; ++i)
        #pragma unroll
        for (int j = 0; j < 2; ++j)
            wmma::fill_fragment(acc[i][j], 0.0f);

    const int aR = tid >> 3;            // 0..31
    const int aC = (tid & 7) << 2;      // 0..28
    const int vR = tid >> 4;            // 0..15
    const int vC = (tid & 15) << 2;     // 0..60

    for (int k0 = 0; k0 < SEQ; k0 += 32) {
        #pragma unroll
        for (int p = 0; p < 4; ++p) {
            const int r = aR + p * 32;
            float* gp = abase + (size_t)(m0 + r) * SEQ + k0 + aC;
            float4 a = *(const float4*)gp;
            const float iv = invs[r];
            a.x *= iv; a.y *= iv; a.z *= iv; a.w *= iv;
            *(float4*)gp = a;                 // normalized attn (final output)
            *(float4*)&As[r][aC] = a;
        }
        #pragma unroll
        for (int p = 0; p < 2; ++p) {
            const int r = vR + p * 16;
            *(float4*)&Vs[r][vC] =
                *(const float4*)(vbase + (size_t)(k0 + r) * DM + vC);
        }
        __syncthreads();

        #pragma unroll
        for (int kk = 0; kk < 32; kk += 8) {
            wmma::fragment<wmma::matrix_a, 16, 16, 8, wmma::precision::tf32,
                           wmma::row_major> af[2];
            wmma::fragment<wmma::matrix_b, 16, 16, 8, wmma::precision::tf32,
                           wmma::row_major> bf[2];
            #pragma unroll
            for (int i = 0; i < 2; ++i) {
                wmma::load_matrix_sync(af[i], &As[wm + i * 16][kk], 36);
                frag_to_tf32(af[i]);
            }
            #pragma unroll
            for (int j = 0; j < 2; ++j) {
                wmma::load_matrix_sync(bf[j], &Vs[kk][wn + j * 16], 72);
                frag_to_tf32(bf[j]);
            }
            #pragma unroll
            for (int i = 0; i < 2; ++i)
                #pragma unroll
                for (int j = 0; j < 2; ++j)
                    wmma::mma_sync(acc[i][j], af[i], bf[j], acc[i][j]);
        }
        __syncthreads();
    }

    #pragma unroll
    for (int i = 0; i < 2; ++i)
        #pragma unroll
        for (int j = 0; j < 2; ++j)
            wmma::store_matrix_sync(
                ctx + (size_t)(b * SEQ + m0 + wm + i * 16) * DM
                    + h * DEPTH + wn + j * 16,
                acc[i][j], DM, wmma::mem_row_major);
}

// ---------------------------------------------------------------------------
extern "C" void kernel_launch(void* const* d_in, const int* in_sizes, int n_in,
                              void* d_out, int out_size)
{
    const float* query = (const float*)d_in[0];
    const float* key   = (const float*)d_in[1];
    const float* value = (const float*)d_in[2];
    const float* Wq = (const float*)d_in[3];
    const float* bq = (const float*)d_in[4];
    const float* Wk = (const float*)d_in[5];
    const float* bk = (const float*)d_in[6];
    const float* Wv = (const float*)d_in[7];
    const float* bv = (const float*)d_in[8];
    const float* Wo = (const float*)d_in[9];
    const float* bo = (const float*)d_in[10];

    float* out  = (float*)d_out;
    float* attn = out + (size_t)BATCH * SEQ * DM;

    float *q, *k, *v, *ctx, *partial, *rowinv;
    cudaGetSymbolAddress((void**)&q,       g_q);
    cudaGetSymbolAddress((void**)&k,       g_k);
    cudaGetSymbolAddress((void**)&v,       g_v);
    cudaGetSymbolAddress((void**)&ctx,     g_ctx);
    cudaGetSymbolAddress((void**)&partial, g_partial);
    cudaGetSymbolAddress((void**)&rowinv,  g_rowinv);

    dim3 gproj(DM / 128, MROWS / 128);   // (8, 32)
    proj_gemm_tf32<<<gproj, 256>>>(query, Wq, bq, q, MROWS, DM, DM);
    proj_gemm_tf32<<<gproj, 256>>>(key,   Wk, bk, k, MROWS, DM, DM);
    proj_gemm_tf32<<<gproj, 256>>>(value, Wv, bv, v, MROWS, DM, DM);

    dim3 gsc(SEQ / 128, SEQ / 128, BATCH * NH);  // (16, 16, 32)
    scores_exp_tf32<<<gsc, 256>>>(q, k, attn, partial);

    rowinv_kernel<<<NROWS / 256, 256>>>(partial, rowinv);

    dim3 gctx(1, SEQ / 128, BATCH * NH);         // (1, 16, 32)
    ctx_norm_tf32<<<gctx, 256>>>(attn, v, rowinv, ctx);

    proj_gemm_tf32<<<gproj, 256>>>(ctx, Wo, bo, out, MROWS, DM, DM);
}

// round 5
// speedup vs baseline: 1.0631x; 1.0517x over previous
#include <cuda_runtime.h>
#include <mma.h>
#include <math.h>

using namespace nvcuda;

#define BATCH 2
#define SEQ   2048
#define DM    1024
#define NH    16
#define DEPTH 64
#define MROWS (BATCH * SEQ)       // 4096
#define NROWS (BATCH * NH * SEQ)  // 65536 attention rows

// Scratch (allocation-free rule: __device__ globals)
__device__ float g_q[BATCH * SEQ * DM];
__device__ float g_k[BATCH * SEQ * DM];
__device__ float g_v[BATCH * SEQ * DM];
__device__ float g_ctx[BATCH * SEQ * DM];
__device__ float g_rowinv[NROWS];

template <class Frag>
__device__ __forceinline__ void frag_to_tf32(Frag& f) {
    #pragma unroll
    for (int i = 0; i < f.num_elements; ++i)
        f.x[i] = wmma::__float_to_tf32(f.x[i]);
}

// ---------------------------------------------------------------------------
// TF32 GEMM + bias body (R2 config: 256 thr, 8 warps 4x2, warp 32x64, BK=32)
// ---------------------------------------------------------------------------
__device__ __forceinline__
void gemm_body(const float* __restrict__ A, const float* __restrict__ W,
               const float* __restrict__ bias, float* __restrict__ C,
               int M, int N, int K, int bx, int by)
{
    __shared__ float As[128][36];    // [m][k]
    __shared__ float Bs[32][132];    // [k][n]
    __shared__ float BiasS[16][132];

    const int tid  = threadIdx.x;
    const int wid  = tid >> 5;
    const int brow = by * 128;
    const int bcol = bx * 128;
    const int wm   = (wid >> 1) * 32;
    const int wn   = (wid & 1) * 64;

    #pragma unroll
    for (int p = 0; p < 8; ++p) {
        const int f = tid + p * 256;
        BiasS[f >> 7][f & 127] = bias[bcol + (f & 127)];
    }
    __syncthreads();

    wmma::fragment<wmma::accumulator, 16, 16, 8, float> acc[2][4];
    #pragma unroll
    for (int i = 0; i < 2; ++i)
        #pragma unroll
        for (int j = 0; j < 4; ++j)
            wmma::load_matrix_sync(acc[i][j], &BiasS[0][wn + j * 16], 132,
                                   wmma::mem_row_major);

    const int aR = tid >> 3;
    const int aC = (tid & 7) << 2;
    const int bR = tid >> 5;
    const int bC = (tid & 31) << 2;

    for (int k0 = 0; k0 < K; k0 += 32) {
        #pragma unroll
        for (int p = 0; p < 4; ++p) {
            const int r = aR + p * 32;
            *(float4*)&As[r][aC] =
                *(const float4*)(A + (size_t)(brow + r) * K + k0 + aC);
        }
        #pragma unroll
        for (int p = 0; p < 4; ++p) {
            const int r = bR + p * 8;
            *(float4*)&Bs[r][bC] =
                *(const float4*)(W + (size_t)(k0 + r) * N + bcol + bC);
        }
        __syncthreads();

        #pragma unroll
        for (int kk = 0; kk < 32; kk += 8) {
            wmma::fragment<wmma::matrix_a, 16, 16, 8, wmma::precision::tf32,
                           wmma::row_major> af[2];
            wmma::fragment<wmma::matrix_b, 16, 16, 8, wmma::precision::tf32,
                           wmma::row_major> bf[4];
            #pragma unroll
            for (int i = 0; i < 2; ++i) {
                wmma::load_matrix_sync(af[i], &As[wm + i * 16][kk], 36);
                frag_to_tf32(af[i]);
            }
            #pragma unroll
            for (int j = 0; j < 4; ++j) {
                wmma::load_matrix_sync(bf[j], &Bs[kk][wn + j * 16], 132);
                frag_to_tf32(bf[j]);
            }
            #pragma unroll
            for (int i = 0; i < 2; ++i)
                #pragma unroll
                for (int j = 0; j < 4; ++j)
                    wmma::mma_sync(acc[i][j], af[i], bf[j], acc[i][j]);
        }
        __syncthreads();
    }

    #pragma unroll
    for (int i = 0; i < 2; ++i)
        #pragma unroll
        for (int j = 0; j < 4; ++j)
            wmma::store_matrix_sync(
                C + (size_t)(brow + wm + i * 16) * N + bcol + wn + j * 16,
                acc[i][j], N, wmma::mem_row_major);
}

// QKV fused projections: gridDim.z selects which of the three GEMMs.
__global__ __launch_bounds__(256)
void qkv_proj_tf32(const float* __restrict__ query, const float* __restrict__ key,
                   const float* __restrict__ value,
                   const float* __restrict__ Wq, const float* __restrict__ bq,
                   const float* __restrict__ Wk, const float* __restrict__ bk,
                   const float* __restrict__ Wv, const float* __restrict__ bv,
                   float* __restrict__ q, float* __restrict__ k,
                   float* __restrict__ v)
{
    const int z = blockIdx.z;
    const float* A    = (z == 0) ? query : (z == 1) ? key : value;
    const float* W    = (z == 0) ? Wq    : (z == 1) ? Wk  : Wv;
    const float* bias = (z == 0) ? bq    : (z == 1) ? bk  : bv;
    float*       C    = (z == 0) ? q     : (z == 1) ? k   : v;
    gemm_body(A, W, bias, C, MROWS, DM, DM, blockIdx.x, blockIdx.y);
}

__global__ __launch_bounds__(256)
void o_proj_tf32(const float* __restrict__ A, const float* __restrict__ W,
                 const float* __restrict__ bias, float* __restrict__ C)
{
    gemm_body(A, W, bias, C, MROWS, DM, DM, blockIdx.x, blockIdx.y);
}

// ---------------------------------------------------------------------------
// Fused attention: per block = (bh, 128 query rows). Loops over all 16
// 128-wide key tiles: S = (Q*0.125) K^T  ->  E = exp(S) (written unnormalized
// to attn gmem)  ->  ctx_unnorm += E V, row sums in registers. At the end:
// rowinv computed in-block, ctx scaled and stored, rowinv saved for the
// attn-normalize pass.
// Dynamic smem: Qs[128][68] | KE[128][132] (K tile aliased by E tile) |
//               Vs[128][68]  = 137.2 KB
// ---------------------------------------------------------------------------
#define QS_OFF  0
#define KE_OFF  (128 * 68)              // 8704
#define VS_OFF  (128 * 68 + 128 * 132)  // 25600
#define SM_FLOATS (VS_OFF + 128 * 68)   // 34304 floats = 137216 B

__global__ __launch_bounds__(256)
void attn_fused_tf32(const float* __restrict__ q, const float* __restrict__ k,
                     const float* __restrict__ v, float* __restrict__ attn,
                     float* __restrict__ rowinv_g, float* __restrict__ ctx)
{
    extern __shared__ float sm[];
    float* Qs = sm + QS_OFF;   // [128][68]
    float* KE = sm + KE_OFF;   // [128][132]  K tile, then E tile
    float* Vs = sm + VS_OFF;   // [128][68]
    __shared__ float psum[128];

    const int bh = blockIdx.y;
    const int b  = bh >> 4;
    const int h  = bh & 15;
    const int i0 = blockIdx.x * 128;
    const int tid  = threadIdx.x;
    const int lane = tid & 31;
    const int wid  = tid >> 5;
    const int wm   = (wid >> 1) * 32;   // rows (S and ctx)
    const int wn   = (wid & 1) * 64;    // S cols
    const int cn   = (wid & 1) * 32;    // ctx cols

    const float* qbase = q + (size_t)b * SEQ * DM + h * DEPTH;
    const float* kbase = k + (size_t)b * SEQ * DM + h * DEPTH;
    const float* vbase = v + (size_t)b * SEQ * DM + h * DEPTH;
    float* obase = attn + (size_t)bh * SEQ * SEQ;

    if (tid < 128) psum[tid] = 0.0f;

    // Load Q tile once, scale folded (exact: *2^-3)
    const int lR = tid >> 4;            // 0..15
    const int lC = (tid & 15) << 2;     // 0..60
    #pragma unroll
    for (int p = 0; p < 8; ++p) {
        const int r = lR + p * 16;
        float4 t = *(const float4*)(qbase + (size_t)(i0 + r) * DM + lC);
        t.x *= 0.125f; t.y *= 0.125f; t.z *= 0.125f; t.w *= 0.125f;
        *(float4*)&Qs[r * 68 + lC] = t;
    }

    wmma::fragment<wmma::accumulator, 16, 16, 8, float> cacc[2][2];
    #pragma unroll
    for (int i = 0; i < 2; ++i)
        #pragma unroll
        for (int j = 0; j < 2; ++j)
            wmma::fill_fragment(cacc[i][j], 0.0f);

    float lo[2] = {0.0f, 0.0f};   // rowsum, row = wm + i*16 + (lane>>2)
    float hi[2] = {0.0f, 0.0f};   // rowsum, row = wm + i*16 + 8 + (lane>>2)

    for (int jt = 0; jt < 16; ++jt) {
        const int j0 = jt * 128;

        __syncthreads();   // prev PV done: KE/Vs free (1st iter: trivial)
        #pragma unroll
        for (int p = 0; p < 8; ++p) {
            const int r = lR + p * 16;
            *(float4*)&KE[r * 132 + lC] =
                *(const float4*)(kbase + (size_t)(j0 + r) * DM + lC);
            *(float4*)&Vs[r * 68 + lC] =
                *(const float4*)(vbase + (size_t)(j0 + r) * DM + lC);
        }
        __syncthreads();   // K,V (and on 1st iter Q) visible

        // S = Q K^T : warp tile 32x64
        wmma::fragment<wmma::accumulator, 16, 16, 8, float> sacc[2][4];
        #pragma unroll
        for (int i = 0; i < 2; ++i)
            #pragma unroll
            for (int j = 0; j < 4; ++j)
                wmma::fill_fragment(sacc[i][j], 0.0f);

        #pragma unroll
        for (int kk = 0; kk < DEPTH; kk += 8) {
            wmma::fragment<wmma::matrix_a, 16, 16, 8, wmma::precision::tf32,
                           wmma::row_major> af[2];
            wmma::fragment<wmma::matrix_b, 16, 16, 8, wmma::precision::tf32,
                           wmma::col_major> bf[4];
            #pragma unroll
            for (int i = 0; i < 2; ++i) {
                wmma::load_matrix_sync(af[i], &Qs[(wm + i * 16) * 68 + kk], 68);
                frag_to_tf32(af[i]);
            }
            #pragma unroll
            for (int j = 0; j < 4; ++j) {
                wmma::load_matrix_sync(bf[j], &KE[(wn + j * 16) * 132 + kk], 132);
                frag_to_tf32(bf[j]);
            }
            #pragma unroll
            for (int i = 0; i < 2; ++i)
                #pragma unroll
                for (int j = 0; j < 4; ++j)
                    wmma::mma_sync(sacc[i][j], af[i], bf[j], sacc[i][j]);
        }

        // E = exp(S): registers; rowsums; unnormalized store to attn gmem
        #pragma unroll
        for (int i = 0; i < 2; ++i)
            #pragma unroll
            for (int j = 0; j < 4; ++j) {
                #pragma unroll
                for (int e = 0; e < 8; ++e) {
                    const float x = __expf(sacc[i][j].x[e]);
                    sacc[i][j].x[e] = x;
                    if ((e & 3) < 2) lo[i] += x; else hi[i] += x;
                }
                wmma::store_matrix_sync(
                    obase + (size_t)(i0 + wm + i * 16) * SEQ + j0 + wn + j * 16,
                    sacc[i][j], SEQ, wmma::mem_row_major);
            }

        __syncthreads();   // all warps done reading K from KE

        #pragma unroll
        for (int i = 0; i < 2; ++i)
            #pragma unroll
            for (int j = 0; j < 4; ++j)
                wmma::store_matrix_sync(&KE[(wm + i * 16) * 132 + wn + j * 16],
                                        sacc[i][j], 132, wmma::mem_row_major);
        __syncthreads();   // E tile visible

        // ctx += E V : warp tile 32x32, K-dim = 128
        #pragma unroll
        for (int kk = 0; kk < 128; kk += 8) {
            wmma::fragment<wmma::matrix_a, 16, 16, 8, wmma::precision::tf32,
                           wmma::row_major> af[2];
            wmma::fragment<wmma::matrix_b, 16, 16, 8, wmma::precision::tf32,
                           wmma::row_major> bf[2];
            #pragma unroll
            for (int i = 0; i < 2; ++i) {
                wmma::load_matrix_sync(af[i], &KE[(wm + i * 16) * 132 + kk], 132);
                frag_to_tf32(af[i]);
            }
            #pragma unroll
            for (int j = 0; j < 2; ++j) {
                wmma::load_matrix_sync(bf[j], &Vs[kk * 68 + cn + j * 16], 68);
                frag_to_tf32(bf[j]);
            }
            #pragma unroll
            for (int i = 0; i < 2; ++i)
                #pragma unroll
                for (int j = 0; j < 2; ++j)
                    wmma::mma_sync(cacc[i][j], af[i], bf[j], cacc[i][j]);
        }
    }

    // Row sums -> rowinv (deterministic: fixed shfl tree + commutative adds)
    #pragma unroll
    for (int i = 0; i < 2; ++i) {
        lo[i] += __shfl_xor_sync(0xffffffffu, lo[i], 1);
        lo[i] += __shfl_xor_sync(0xffffffffu, lo[i], 2);
        hi[i] += __shfl_xor_sync(0xffffffffu, hi[i], 1);
        hi[i] += __shfl_xor_sync(0xffffffffu, hi[i], 2);
    }
    __syncthreads();   // psum zeros (written at start) visible for sure
    if ((lane & 3) == 0) {
        const int g = lane >> 2;
        #pragma unroll
        for (int i = 0; i < 2; ++i) {
            atomicAdd(&psum[wm + i * 16 + g],     lo[i]);
            atomicAdd(&psum[wm + i * 16 + 8 + g], hi[i]);
        }
    }
    __syncthreads();
    if (tid < 128) {
        const float inv = 1.0f / psum[tid];
        psum[tid] = inv;
        rowinv_g[(size_t)bh * SEQ + i0 + tid] = inv;
    }
    __syncthreads();

    // Scale ctx accumulators by rowinv and store
    const int g = lane >> 2;
    #pragma unroll
    for (int i = 0; i < 2; ++i) {
        const float ivlo = psum[wm + i * 16 + g];
        const float ivhi = psum[wm + i * 16 + 8 + g];
        #pragma unroll
        for (int j = 0; j < 2; ++j) {
            #pragma unroll
            for (int e = 0; e < 8; ++e)
                cacc[i][j].x[e] *= ((e & 3) < 2) ? ivlo : ivhi;
            wmma::store_matrix_sync(
                ctx + (size_t)(b * SEQ + i0 + wm + i * 16) * DM
                    + h * DEPTH + cn + j * 16,
                cacc[i][j], DM, wmma::mem_row_major);
        }
    }
}

// ---------------------------------------------------------------------------
// attn normalize in place: one block per attention row.
// ---------------------------------------------------------------------------
__global__ __launch_bounds__(256)
void attn_norm_kernel(float* __restrict__ attn, const float* __restrict__ rowinv)
{
    const float inv = rowinv[blockIdx.x];
    float4* p = (float4*)(attn + (size_t)blockIdx.x * SEQ);
    const int tid = threadIdx.x;
    float4 a = p[tid], b = p[tid + 256];
    a.x *= inv; a.y *= inv; a.z *= inv; a.w *= inv;
    b.x *= inv; b.y *= inv; b.z *= inv; b.w *= inv;
    p[tid] = a; p[tid + 256] = b;
}

// ---------------------------------------------------------------------------
extern "C" void kernel_launch(void* const* d_in, const int* in_sizes, int n_in,
                              void* d_out, int out_size)
{
    const float* query = (const float*)d_in[0];
    const float* key   = (const float*)d_in[1];
    const float* value = (const float*)d_in[2];
    const float* Wq = (const float*)d_in[3];
    const float* bq = (const float*)d_in[4];
    const float* Wk = (const float*)d_in[5];
    const float* bk = (const float*)d_in[6];
    const float* Wv = (const float*)d_in[7];
    const float* bv = (const float*)d_in[8];
    const float* Wo = (const float*)d_in[9];
    const float* bo = (const float*)d_in[10];

    float* out  = (float*)d_out;
    float* attn = out + (size_t)BATCH * SEQ * DM;

    float *q, *k, *v, *ctx, *rowinv;
    cudaGetSymbolAddress((void**)&q,      g_q);
    cudaGetSymbolAddress((void**)&k,      g_k);
    cudaGetSymbolAddress((void**)&v,      g_v);
    cudaGetSymbolAddress((void**)&ctx,    g_ctx);
    cudaGetSymbolAddress((void**)&rowinv, g_rowinv);

    static int init_done = 0;
    if (!init_done) {
        cudaFuncSetAttribute(attn_fused_tf32,
                             cudaFuncAttributeMaxDynamicSharedMemorySize,
                             SM_FLOATS * 4);
        init_done = 1;
    }

    dim3 gqkv(DM / 128, MROWS / 128, 3);   // (8, 32, 3)
    qkv_proj_tf32<<<gqkv, 256>>>(query, key, value, Wq, bq, Wk, bk, Wv, bv,
                                 q, k, v);

    dim3 gatt(SEQ / 128, BATCH * NH);      // (16, 32)
    attn_fused_tf32<<<gatt, 256, SM_FLOATS * 4>>>(q, k, v, attn, rowinv, ctx);

    attn_norm_kernel<<<NROWS, 256>>>(attn, rowinv);

    dim3 gproj(DM / 128, MROWS / 128);     // (8, 32)
    o_proj_tf32<<<gproj, 256>>>(ctx, Wo, bo, out);
}

// round 7
// speedup vs baseline: 1.2534x; 1.1791x over previous
#include <cuda_runtime.h>
#include <mma.h>
#include <math.h>
#include <stdint.h>

using namespace nvcuda;

#define BATCH 2
#define SEQ   2048
#define DM    1024
#define NH    16
#define DEPTH 64
#define MROWS (BATCH * SEQ)       // 4096
#define NROWS (BATCH * NH * SEQ)  // 65536 attention rows

// Scratch (allocation-free rule: __device__ globals)
__device__ float g_q[BATCH * SEQ * DM];
__device__ float g_k[BATCH * SEQ * DM];
__device__ float g_v[BATCH * SEQ * DM];
__device__ float g_ctx[BATCH * SEQ * DM];
__device__ float g_rowinv[NROWS];
// TF32-pre-rounded copies of inputs and weights
__device__ float g_rin[3][BATCH * SEQ * DM];
__device__ float g_rw[4][DM * DM];

__device__ __forceinline__ void cp_async16(void* smem, const void* gmem) {
    unsigned int s = (unsigned int)__cvta_generic_to_shared(smem);
    asm volatile("cp.async.cg.shared.global [%0], [%1], 16;\n" :: "r"(s), "l"(gmem));
}
__device__ __forceinline__ void cp_commit() {
    asm volatile("cp.async.commit_group;\n");
}
template <int N>
__device__ __forceinline__ void cp_wait() {
    asm volatile("cp.async.wait_group %0;\n" :: "n"(N));
}

// ---------------------------------------------------------------------------
// Round fp32 -> tf32 (RN), elementwise. n must be /4.
// ---------------------------------------------------------------------------
__global__ __launch_bounds__(256)
void round_tf32_kernel(const float* __restrict__ in, float* __restrict__ out,
                       int n4)
{
    const int stride = gridDim.x * 256;
    for (int i = blockIdx.x * 256 + threadIdx.x; i < n4; i += stride) {
        float4 v = ((const float4*)in)[i];
        v.x = wmma::__float_to_tf32(v.x);
        v.y = wmma::__float_to_tf32(v.y);
        v.z = wmma::__float_to_tf32(v.z);
        v.w = wmma::__float_to_tf32(v.w);
        ((float4*)out)[i] = v;
    }
}

// ---------------------------------------------------------------------------
// TF32 GEMM + bias, cp.async 2-stage pipeline, NO in-loop conversions.
// Block 128x128, BK=32, 256 thr, 8 warps (4m x 2n), warp 32x64, 2 blocks/SM.
// Dynamic smem: As[2][128][36] | Bs[2][32][132] | BiasS[16][132]  = 79104 B
// ---------------------------------------------------------------------------
#define GE_AS(s,r,c)  sm[(s) * 4608 + (r) * 36 + (c)]
#define GE_BS(s,r,c)  sm[9216 + (s) * 4224 + (r) * 132 + (c)]
#define GE_BIAS(r,c)  sm[17664 + (r) * 132 + (c)]
#define GE_SMEM_BYTES ((17664 + 16 * 132) * 4)

template <bool ROUND_OUT>
__device__ __forceinline__
void gemm_body(const float* __restrict__ A, const float* __restrict__ W,
               const float* __restrict__ bias, float* __restrict__ C,
               int K, int N, int bx, int by)
{
    extern __shared__ float sm[];

    const int tid  = threadIdx.x;
    const int wid  = tid >> 5;
    const int brow = by * 128;
    const int bcol = bx * 128;
    const int wm   = (wid >> 1) * 32;
    const int wn   = (wid & 1) * 64;

    const int aR = tid >> 3;            // 0..31
    const int aC = (tid & 7) << 2;      // 0..28
    const int bR = tid >> 5;            // 0..7
    const int bC = (tid & 31) << 2;     // 0..124

    // Prefetch chunk 0 into stage 0
    {
        #pragma unroll
        for (int p = 0; p < 4; ++p)
            cp_async16(&GE_AS(0, aR + p * 32, aC),
                       A + (size_t)(brow + aR + p * 32) * K + aC);
        #pragma unroll
        for (int p = 0; p < 4; ++p)
            cp_async16(&GE_BS(0, bR + p * 8, bC),
                       W + (size_t)(bR + p * 8) * N + bcol + bC);
        cp_commit();
    }

    #pragma unroll
    for (int p = 0; p < 8; ++p) {
        const int f = tid + p * 256;
        GE_BIAS(f >> 7, f & 127) = bias[bcol + (f & 127)];
    }
    __syncthreads();

    wmma::fragment<wmma::accumulator, 16, 16, 8, float> acc[2][4];
    #pragma unroll
    for (int i = 0; i < 2; ++i)
        #pragma unroll
        for (int j = 0; j < 4; ++j)
            wmma::load_matrix_sync(acc[i][j], &GE_BIAS(0, wn + j * 16), 132,
                                   wmma::mem_row_major);

    const int NCH = K / 32;
    for (int c = 0; c < NCH; ++c) {
        if (c + 1 < NCH) {
            const int s = (c + 1) & 1;
            const int k0 = (c + 1) * 32;
            #pragma unroll
            for (int p = 0; p < 4; ++p)
                cp_async16(&GE_AS(s, aR + p * 32, aC),
                           A + (size_t)(brow + aR + p * 32) * K + k0 + aC);
            #pragma unroll
            for (int p = 0; p < 4; ++p)
                cp_async16(&GE_BS(s, bR + p * 8, bC),
                           W + (size_t)(k0 + bR + p * 8) * N + bcol + bC);
            cp_commit();
            cp_wait<1>();
        } else {
            cp_wait<0>();
        }
        __syncthreads();

        const int s = c & 1;
        #pragma unroll
        for (int kk = 0; kk < 32; kk += 8) {
            wmma::fragment<wmma::matrix_a, 16, 16, 8, wmma::precision::tf32,
                           wmma::row_major> af[2];
            wmma::fragment<wmma::matrix_b, 16, 16, 8, wmma::precision::tf32,
                           wmma::row_major> bf[4];
            #pragma unroll
            for (int i = 0; i < 2; ++i)
                wmma::load_matrix_sync(af[i], &GE_AS(s, wm + i * 16, kk), 36);
            #pragma unroll
            for (int j = 0; j < 4; ++j)
                wmma::load_matrix_sync(bf[j], &GE_BS(s, kk, wn + j * 16), 132);
            #pragma unroll
            for (int i = 0; i < 2; ++i)
                #pragma unroll
                for (int j = 0; j < 4; ++j)
                    wmma::mma_sync(acc[i][j], af[i], bf[j], acc[i][j]);
        }
        __syncthreads();   // stage free before prefetch c+2 overwrites it
    }

    #pragma unroll
    for (int i = 0; i < 2; ++i)
        #pragma unroll
        for (int j = 0; j < 4; ++j) {
            if (ROUND_OUT)
                #pragma unroll
                for (int e = 0; e < 8; ++e)
                    acc[i][j].x[e] = wmma::__float_to_tf32(acc[i][j].x[e]);
            wmma::store_matrix_sync(
                C + (size_t)(brow + wm + i * 16) * N + bcol + wn + j * 16,
                acc[i][j], N, wmma::mem_row_major);
        }
}

// QKV fused projections: gridDim.z selects which GEMM. Outputs tf32-rounded.
__global__ __launch_bounds__(256, 2)
void qkv_proj_tf32(const float* __restrict__ Wq_r, const float* __restrict__ bq,
                   const float* __restrict__ Wk_r, const float* __restrict__ bk,
                   const float* __restrict__ Wv_r, const float* __restrict__ bv,
                   float* __restrict__ q, float* __restrict__ k,
                   float* __restrict__ v)
{
    const int z = blockIdx.z;
    const float* A    = g_rin[z];
    const float* W    = (z == 0) ? Wq_r : (z == 1) ? Wk_r : Wv_r;
    const float* bias = (z == 0) ? bq   : (z == 1) ? bk   : bv;
    float*       C    = (z == 0) ? q    : (z == 1) ? k    : v;
    gemm_body<true>(A, W, bias, C, DM, DM, blockIdx.x, blockIdx.y);
}

__global__ __launch_bounds__(256, 2)
void o_proj_tf32(const float* __restrict__ A, const float* __restrict__ W,
                 const float* __restrict__ bias, float* __restrict__ C)
{
    gemm_body<false>(A, W, bias, C, DM, DM, blockIdx.x, blockIdx.y);
}

// ---------------------------------------------------------------------------
// Fused attention (operands pre-rounded tf32 -> no in-loop conversions).
// Per block = (bh, 128 query rows); loops 16 key tiles:
//   S = (Q*0.125) K^T -> raw exp to attn gmem, tf32 exp to smem -> ctx += E V.
// Row sums in registers; ctx scaled by 1/rowsum in-block (tf32-rounded out).
// Dynamic smem: Qs[128][68] | KE[128][132] | Vs[128][68] = 137216 B
// ---------------------------------------------------------------------------
#define QS_OFF  0
#define KE_OFF  (128 * 68)
#define VS_OFF  (128 * 68 + 128 * 132)
#define SM_FLOATS (VS_OFF + 128 * 68)

__global__ __launch_bounds__(256)
void attn_fused_tf32(const float* __restrict__ q, const float* __restrict__ k,
                     const float* __restrict__ v, float* __restrict__ attn,
                     float* __restrict__ rowinv_g, float* __restrict__ ctx)
{
    extern __shared__ float sm[];
    float* Qs = sm + QS_OFF;   // [128][68]
    float* KE = sm + KE_OFF;   // [128][132]  K tile, then E tile
    float* Vs = sm + VS_OFF;   // [128][68]
    __shared__ float psum[128];

    const int bh = blockIdx.y;
    const int b  = bh >> 4;
    const int h  = bh & 15;
    const int i0 = blockIdx.x * 128;
    const int tid  = threadIdx.x;
    const int lane = tid & 31;
    const int wid  = tid >> 5;
    const int wm   = (wid >> 1) * 32;
    const int wn   = (wid & 1) * 64;
    const int cn   = (wid & 1) * 32;

    const float* qbase = q + (size_t)b * SEQ * DM + h * DEPTH;
    const float* kbase = k + (size_t)b * SEQ * DM + h * DEPTH;
    const float* vbase = v + (size_t)b * SEQ * DM + h * DEPTH;
    float* obase = attn + (size_t)bh * SEQ * SEQ;

    if (tid < 128) psum[tid] = 0.0f;

    // Q tile once; *0.125 is an exact exponent shift (stays tf32)
    const int lR = tid >> 4;            // 0..15
    const int lC = (tid & 15) << 2;     // 0..60
    #pragma unroll
    for (int p = 0; p < 8; ++p) {
        const int r = lR + p * 16;
        float4 t = *(const float4*)(qbase + (size_t)(i0 + r) * DM + lC);
        t.x *= 0.125f; t.y *= 0.125f; t.z *= 0.125f; t.w *= 0.125f;
        *(float4*)&Qs[r * 68 + lC] = t;
    }

    wmma::fragment<wmma::accumulator, 16, 16, 8, float> cacc[2][2];
    #pragma unroll
    for (int i = 0; i < 2; ++i)
        #pragma unroll
        for (int j = 0; j < 2; ++j)
            wmma::fill_fragment(cacc[i][j], 0.0f);

    float lo[2] = {0.0f, 0.0f};
    float hi[2] = {0.0f, 0.0f};

    for (int jt = 0; jt < 16; ++jt) {
        const int j0 = jt * 128;

        __syncthreads();   // prev PV done: KE/Vs free
        #pragma unroll
        for (int p = 0; p < 8; ++p) {
            const int r = lR + p * 16;
            *(float4*)&KE[r * 132 + lC] =
                *(const float4*)(kbase + (size_t)(j0 + r) * DM + lC);
            *(float4*)&Vs[r * 68 + lC] =
                *(const float4*)(vbase + (size_t)(j0 + r) * DM + lC);
        }
        __syncthreads();

        // S = Q K^T
        wmma::fragment<wmma::accumulator, 16, 16, 8, float> sacc[2][4];
        #pragma unroll
        for (int i = 0; i < 2; ++i)
            #pragma unroll
            for (int j = 0; j < 4; ++j)
                wmma::fill_fragment(sacc[i][j], 0.0f);

        #pragma unroll
        for (int kk = 0; kk < DEPTH; kk += 8) {
            wmma::fragment<wmma::matrix_a, 16, 16, 8, wmma::precision::tf32,
                           wmma::row_major> af[2];
            wmma::fragment<wmma::matrix_b, 16, 16, 8, wmma::precision::tf32,
                           wmma::col_major> bf[4];
            #pragma unroll
            for (int i = 0; i < 2; ++i)
                wmma::load_matrix_sync(af[i], &Qs[(wm + i * 16) * 68 + kk], 68);
            #pragma unroll
            for (int j = 0; j < 4; ++j)
                wmma::load_matrix_sync(bf[j], &KE[(wn + j * 16) * 132 + kk], 132);
            #pragma unroll
            for (int i = 0; i < 2; ++i)
                #pragma unroll
                for (int j = 0; j < 4; ++j)
                    wmma::mma_sync(sacc[i][j], af[i], bf[j], sacc[i][j]);
        }

        // exp: raw fp32 -> gmem + rowsums; tf32-rounded -> eacc for EV mma
        wmma::fragment<wmma::accumulator, 16, 16, 8, float> eacc[2][4];
        #pragma unroll
        for (int i = 0; i < 2; ++i)
            #pragma unroll
            for (int j = 0; j < 4; ++j) {
                #pragma unroll
                for (int e = 0; e < 8; ++e) {
                    const float x = __expf(sacc[i][j].x[e]);
                    sacc[i][j].x[e] = x;
                    eacc[i][j].x[e] = wmma::__float_to_tf32(x);
                    if ((e & 3) < 2) lo[i] += x; else hi[i] += x;
                }
                wmma::store_matrix_sync(
                    obase + (size_t)(i0 + wm + i * 16) * SEQ + j0 + wn + j * 16,
                    sacc[i][j], SEQ, wmma::mem_row_major);
            }

        __syncthreads();   // all warps done reading K from KE

        #pragma unroll
        for (int i = 0; i < 2; ++i)
            #pragma unroll
            for (int j = 0; j < 4; ++j)
                wmma::store_matrix_sync(&KE[(wm + i * 16) * 132 + wn + j * 16],
                                        eacc[i][j], 132, wmma::mem_row_major);
        __syncthreads();

        // ctx += E V
        #pragma unroll
        for (int kk = 0; kk < 128; kk += 8) {
            wmma::fragment<wmma::matrix_a, 16, 16, 8, wmma::precision::tf32,
                           wmma::row_major> af[2];
            wmma::fragment<wmma::matrix_b, 16, 16, 8, wmma::precision::tf32,
                           wmma::row_major> bf[2];
            #pragma unroll
            for (int i = 0; i < 2; ++i)
                wmma::load_matrix_sync(af[i], &KE[(wm + i * 16) * 132 + kk], 132);
            #pragma unroll
            for (int j = 0; j < 2; ++j)
                wmma::load_matrix_sync(bf[j], &Vs[kk * 68 + cn + j * 16], 68);
            #pragma unroll
            for (int i = 0; i < 2; ++i)
                #pragma unroll
                for (int j = 0; j < 2; ++j)
                    wmma::mma_sync(cacc[i][j], af[i], bf[j], cacc[i][j]);
        }
    }

    // Deterministic rowsum -> rowinv
    #pragma unroll
    for (int i = 0; i < 2; ++i) {
        lo[i] += __shfl_xor_sync(0xffffffffu, lo[i], 1);
        lo[i] += __shfl_xor_sync(0xffffffffu, lo[i], 2);
        hi[i] += __shfl_xor_sync(0xffffffffu, hi[i], 1);
        hi[i] += __shfl_xor_sync(0xffffffffu, hi[i], 2);
    }
    __syncthreads();
    if ((lane & 3) == 0) {
        const int g = lane >> 2;
        #pragma unroll
        for (int i = 0; i < 2; ++i) {
            atomicAdd(&psum[wm + i * 16 + g],     lo[i]);
            atomicAdd(&psum[wm + i * 16 + 8 + g], hi[i]);
        }
    }
    __syncthreads();
    if (tid < 128) {
        const float inv = 1.0f / psum[tid];
        psum[tid] = inv;
        rowinv_g[(size_t)bh * SEQ + i0 + tid] = inv;
    }
    __syncthreads();

    // ctx scale + tf32 round (feeds o_proj) + store
    const int g = lane >> 2;
    #pragma unroll
    for (int i = 0; i < 2; ++i) {
        const float ivlo = psum[wm + i * 16 + g];
        const float ivhi = psum[wm + i * 16 + 8 + g];
        #pragma unroll
        for (int j = 0; j < 2; ++j) {
            #pragma unroll
            for (int e = 0; e < 8; ++e)
                cacc[i][j].x[e] = wmma::__float_to_tf32(
                    cacc[i][j].x[e] * (((e & 3) < 2) ? ivlo : ivhi));
            wmma::store_matrix_sync(
                ctx + (size_t)(b * SEQ + i0 + wm + i * 16) * DM
                    + h * DEPTH + cn + j * 16,
                cacc[i][j], DM, wmma::mem_row_major);
        }
    }
}

// ---------------------------------------------------------------------------
// attn normalize in place: one block per attention row.
// ---------------------------------------------------------------------------
__global__ __launch_bounds__(256)
void attn_norm_kernel(float* __restrict__ attn, const float* __restrict__ rowinv)
{
    const float inv = rowinv[blockIdx.x];
    float4* p = (float4*)(attn + (size_t)blockIdx.x * SEQ);
    const int tid = threadIdx.x;
    float4 a = p[tid], b = p[tid + 256];
    a.x *= inv; a.y *= inv; a.z *= inv; a.w *= inv;
    b.x *= inv; b.y *= inv; b.z *= inv; b.w *= inv;
    p[tid] = a; p[tid + 256] = b;
}

// ---------------------------------------------------------------------------
extern "C" void kernel_launch(void* const* d_in, const int* in_sizes, int n_in,
                              void* d_out, int out_size)
{
    const float* query = (const float*)d_in[0];
    const float* key   = (const float*)d_in[1];
    const float* value = (const float*)d_in[2];
    const float* Wq = (const float*)d_in[3];
    const float* bq = (const float*)d_in[4];
    const float* Wk = (const float*)d_in[5];
    const float* bk = (const float*)d_in[6];
    const float* Wv = (const float*)d_in[7];
    const float* bv = (const float*)d_in[8];
    const float* Wo = (const float*)d_in[9];
    const float* bo = (const float*)d_in[10];

    float* out  = (float*)d_out;
    float* attn = out + (size_t)BATCH * SEQ * DM;

    float *q, *k, *v, *ctx, *rowinv, *rin, *rw;
    cudaGetSymbolAddress((void**)&q,      g_q);
    cudaGetSymbolAddress((void**)&k,      g_k);
    cudaGetSymbolAddress((void**)&v,      g_v);
    cudaGetSymbolAddress((void**)&ctx,    g_ctx);
    cudaGetSymbolAddress((void**)&rowinv, g_rowinv);
    cudaGetSymbolAddress((void**)&rin,    g_rin);
    cudaGetSymbolAddress((void**)&rw,     g_rw);

    static int init_done = 0;
    if (!init_done) {
        cudaFuncSetAttribute(attn_fused_tf32,
                             cudaFuncAttributeMaxDynamicSharedMemorySize,
                             SM_FLOATS * 4);
        cudaFuncSetAttribute(qkv_proj_tf32,
                             cudaFuncAttributeMaxDynamicSharedMemorySize,
                             GE_SMEM_BYTES);
        cudaFuncSetAttribute(o_proj_tf32,
                             cudaFuncAttributeMaxDynamicSharedMemorySize,
                             GE_SMEM_BYTES);
        init_done = 1;
    }

    const int NIN = BATCH * SEQ * DM;   // 4M
    const int NW  = DM * DM;            // 1M

    // Pre-round inputs and weights to tf32 (RN)
    round_tf32_kernel<<<512, 256>>>(query, rin + 0 * (size_t)NIN, NIN / 4);
    round_tf32_kernel<<<512, 256>>>(key,   rin + 1 * (size_t)NIN, NIN / 4);
    round_tf32_kernel<<<512, 256>>>(value, rin + 2 * (size_t)NIN, NIN / 4);
    round_tf32_kernel<<<256, 256>>>(Wq, rw + 0 * (size_t)NW, NW / 4);
    round_tf32_kernel<<<256, 256>>>(Wk, rw + 1 * (size_t)NW, NW / 4);
    round_tf32_kernel<<<256, 256>>>(Wv, rw + 2 * (size_t)NW, NW / 4);
    round_tf32_kernel<<<256, 256>>>(Wo, rw + 3 * (size_t)NW, NW / 4);

    dim3 gqkv(DM / 128, MROWS / 128, 3);   // (8, 32, 3)
    qkv_proj_tf32<<<gqkv, 256, GE_SMEM_BYTES>>>(
        rw + 0 * (size_t)NW, bq, rw + 1 * (size_t)NW, bk,
        rw + 2 * (size_t)NW, bv, q, k, v);

    dim3 gatt(SEQ / 128, BATCH * NH);      // (16, 32)
    attn_fused_tf32<<<gatt, 256, SM_FLOATS * 4>>>(q, k, v, attn, rowinv, ctx);

    attn_norm_kernel<<<NROWS, 256>>>(attn, rowinv);

    dim3 gproj(DM / 128, MROWS / 128);     // (8, 32)
    o_proj_tf32<<<gproj, 256, GE_SMEM_BYTES>>>(ctx, rw + 3 * (size_t)NW, bo, out);
}

// round 9
// speedup vs baseline: 3.1881x; 2.5435x over previous
#include <cuda_runtime.h>
#include <cuda_fp16.h>
#include <mma.h>
#include <math.h>
#include <stdint.h>

using namespace nvcuda;

#define BATCH 2
#define SEQ   2048
#define DM    1024
#define NH    16
#define DEPTH 64
#define MROWS (BATCH * SEQ)       // 4096
#define NROWS (BATCH * NH * SEQ)  // 65536 attention rows

// Scratch (allocation-free rule: __device__ globals)
__device__ __half g_q[BATCH * SEQ * DM];
__device__ __half g_k[BATCH * SEQ * DM];
__device__ __half g_v[BATCH * SEQ * DM];
__device__ __half g_ctx[BATCH * SEQ * DM];
__device__ float  g_rowinv[NROWS];
__device__ __half g_rin[3][BATCH * SEQ * DM];   // fp16 inputs
__device__ __half g_rw[4][DM * DM];             // fp16 weights

__device__ __forceinline__ void cp_async16(void* smem, const void* gmem) {
    unsigned int s = (unsigned int)__cvta_generic_to_shared(smem);
    asm volatile("cp.async.cg.shared.global [%0], [%1], 16;\n" :: "r"(s), "l"(gmem));
}
__device__ __forceinline__ void cp_commit() {
    asm volatile("cp.async.commit_group;\n");
}
template <int N>
__device__ __forceinline__ void cp_wait() {
    asm volatile("cp.async.wait_group %0;\n" :: "n"(N));
}

// ---------------------------------------------------------------------------
// fp32 -> fp16 conversion (RN). n8 = n/8.
// ---------------------------------------------------------------------------
__global__ __launch_bounds__(256)
void f2h_kernel(const float* __restrict__ in, __half* __restrict__ out, int n8)
{
    const int stride = gridDim.x * 256;
    for (int i = blockIdx.x * 256 + threadIdx.x; i < n8; i += stride) {
        float4 a = ((const float4*)in)[2 * i];
        float4 b = ((const float4*)in)[2 * i + 1];
        __half2 h[4];
        h[0] = __floats2half2_rn(a.x, a.y);
        h[1] = __floats2half2_rn(a.z, a.w);
        h[2] = __floats2half2_rn(b.x, b.y);
        h[3] = __floats2half2_rn(b.z, b.w);
        ((uint2*)out)[2 * i]     = *(uint2*)&h[0];
        ((uint2*)out)[2 * i + 1] = *(uint2*)&h[2];
    }
}

// m16n16 f32 accumulator lane mapping (sm_80+ canonical):
//   lane = 4g+t; e0,e1,e4,e5 -> row g; e2,e3,e6,e7 -> row g+8
//   col = 2t + (e&1) + 8*(e>>2)
// Store acc as half to base[row*ldm + col] after adding rbias (per element).
__device__ __forceinline__
void store_acc_half(__half* base, const float* x, int ldm, int lane,
                    float slo, float shi)
{
    const int g = lane >> 2, t = lane & 3;
    __half2 p;
    p = __floats2half2_rn(x[0] * slo, x[1] * slo);
    *(__half2*)(base + (size_t)g * ldm + 2 * t) = p;
    p = __floats2half2_rn(x[2] * shi, x[3] * shi);
    *(__half2*)(base + (size_t)(g + 8) * ldm + 2 * t) = p;
    p = __floats2half2_rn(x[4] * slo, x[5] * slo);
    *(__half2*)(base + (size_t)g * ldm + 2 * t + 8) = p;
    p = __floats2half2_rn(x[6] * shi, x[7] * shi);
    *(__half2*)(base + (size_t)(g + 8) * ldm + 2 * t + 8) = p;
}

// ---------------------------------------------------------------------------
// FP16 GEMM + bias, cp.async 2-stage, block 128x128, BK=32, 256 thr,
// 8 warps (4m x 2n), warp 32x64.
// smem halves: A[2][128][40] | B[2][32][136] ; float bias[128] after.
// ---------------------------------------------------------------------------
#define GA(s,r,c)  smh[(s) * 5120 + (r) * 40 + (c)]
#define GB(s,r,c)  smh[10240 + (s) * 4352 + (r) * 136 + (c)]
#define GE_SMEM_BYTES (18944 * 2 + 128 * 4)

// OUT_HALF: write half with scale; else write float via store_matrix_sync.
template <bool OUT_HALF>
__device__ __forceinline__
void gemm_fp16_body(const __half* __restrict__ A, const __half* __restrict__ W,
                    const float* __restrict__ bias, void* __restrict__ C,
                    int K, int N, int bx, int by, float oscale)
{
    extern __shared__ __half smh[];
    float* sbias = (float*)(smh + 18944);

    const int tid  = threadIdx.x;
    const int lane = tid & 31;
    const int wid  = tid >> 5;
    const int brow = by * 128;
    const int bcol = bx * 128;
    const int wm   = (wid >> 1) * 32;
    const int wn   = (wid & 1) * 64;

    const int aRow = tid >> 2;            // 0..63
    const int aCol = (tid & 3) * 8;       // 0,8,16,24
    const int bRow = tid >> 4;            // 0..15
    const int bCol = (tid & 15) * 8;      // 0..120

    // Prefetch chunk 0
    #pragma unroll
    for (int p = 0; p < 2; ++p)
        cp_async16(&GA(0, aRow + p * 64, aCol),
                   A + (size_t)(brow + aRow + p * 64) * K + aCol);
    #pragma unroll
    for (int p = 0; p < 2; ++p)
        cp_async16(&GB(0, bRow + p * 16, bCol),
                   W + (size_t)(bRow + p * 16) * N + bcol + bCol);
    cp_commit();

    if (tid < 128) sbias[tid] = bias[bcol + tid];

    wmma::fragment<wmma::accumulator, 16, 16, 16, float> acc[2][4];
    #pragma unroll
    for (int i = 0; i < 2; ++i)
        #pragma unroll
        for (int j = 0; j < 4; ++j)
            wmma::fill_fragment(acc[i][j], 0.0f);

    const int NCH = K / 32;
    for (int c = 0; c < NCH; ++c) {
        if (c + 1 < NCH) {
            const int s = (c + 1) & 1;
            const int k0 = (c + 1) * 32;
            #pragma unroll
            for (int p = 0; p < 2; ++p)
                cp_async16(&GA(s, aRow + p * 64, aCol),
                           A + (size_t)(brow + aRow + p * 64) * K + k0 + aCol);
            #pragma unroll
            for (int p = 0; p < 2; ++p)
                cp_async16(&GB(s, bRow + p * 16, bCol),
                           W + (size_t)(k0 + bRow + p * 16) * N + bcol + bCol);
            cp_commit();
            cp_wait<1>();
        } else {
            cp_wait<0>();
        }
        __syncthreads();

        const int s = c & 1;
        #pragma unroll
        for (int kk = 0; kk < 32; kk += 16) {
            wmma::fragment<wmma::matrix_a, 16, 16, 16, __half,
                           wmma::row_major> af[2];
            wmma::fragment<wmma::matrix_b, 16, 16, 16, __half,
                           wmma::row_major> bf[4];
            #pragma unroll
            for (int i = 0; i < 2; ++i)
                wmma::load_matrix_sync(af[i], &GA(s, wm + i * 16, kk), 40);
            #pragma unroll
            for (int j = 0; j < 4; ++j)
                wmma::load_matrix_sync(bf[j], &GB(s, kk, wn + j * 16), 136);
            #pragma unroll
            for (int i = 0; i < 2; ++i)
                #pragma unroll
                for (int j = 0; j < 4; ++j)
                    wmma::mma_sync(acc[i][j], af[i], bf[j], acc[i][j]);
        }
        __syncthreads();
    }

    // Epilogue: add bias (mapping-based), then store.
    const int t = lane & 3;
    #pragma unroll
    for (int i = 0; i < 2; ++i)
        #pragma unroll
        for (int j = 0; j < 4; ++j) {
            const int cb = wn + j * 16 + 2 * t;
            const float b0 = sbias[cb],     b1 = sbias[cb + 1];
            const float b4 = sbias[cb + 8], b5 = sbias[cb + 9];
            acc[i][j].x[0] += b0; acc[i][j].x[1] += b1;
            acc[i][j].x[2] += b0; acc[i][j].x[3] += b1;
            acc[i][j].x[4] += b4; acc[i][j].x[5] += b5;
            acc[i][j].x[6] += b4; acc[i][j].x[7] += b5;
            if (OUT_HALF) {
                __half* out = (__half*)C;
                store_acc_half(out + (size_t)(brow + wm + i * 16) * N
                                   + bcol + wn + j * 16,
                               acc[i][j].x, N, lane, oscale, oscale);
            } else {
                wmma::store_matrix_sync(
                    (float*)C + (size_t)(brow + wm + i * 16) * N
                              + bcol + wn + j * 16,
                    acc[i][j], N, wmma::mem_row_major);
            }
        }
}

// QKV projections: z selects GEMM; q gets *0.125 folded in (exact for scores).
__global__ __launch_bounds__(256)
void qkv_proj_fp16(const float* __restrict__ bq, const float* __restrict__ bk,
                   const float* __restrict__ bv)
{
    const int z = blockIdx.z;
    const __half* A    = g_rin[z];
    const __half* W    = g_rw[z];
    const float* bias  = (z == 0) ? bq : (z == 1) ? bk : bv;
    __half*      C     = (z == 0) ? g_q : (z == 1) ? g_k : g_v;
    const float  scale = (z == 0) ? 0.125f : 1.0f;
    gemm_fp16_body<true>(A, W, bias, C, DM, DM, blockIdx.x, blockIdx.y, scale);
}

__global__ __launch_bounds__(256)
void o_proj_fp16(const float* __restrict__ bias, float* __restrict__ out)
{
    gemm_fp16_body<false>(g_ctx, g_rw[3], bias, out, DM, DM,
                          blockIdx.x, blockIdx.y, 1.0f);
}

// ---------------------------------------------------------------------------
// Fused attention (fp16 operands, fp32 accum). Per block = (bh, 128 q-rows).
// 16 key tiles: S = Qs K^T (Q pre-scaled) -> raw fp32 exp -> attn gmem +
// rowsums; half E -> smem; ctx += E V. End: rowinv, scaled half ctx store.
// smem halves: Qs[128][72] | KE[128][136] (K stride 72 alias, then E) |
//              Vs[128][72]  = 71680 B
// ---------------------------------------------------------------------------
#define FQ_OFF  0
#define FK_OFF  9216
#define FV_OFF  (9216 + 17408)
#define FS_HALVES (9216 + 17408 + 9216)

__global__ __launch_bounds__(256)
void attn_fused_fp16(float* __restrict__ attn, float* __restrict__ rowinv_g)
{
    extern __shared__ __half smh[];
    __half* Qs = smh + FQ_OFF;   // [128][72]
    __half* KE = smh + FK_OFF;   // K: [128] stride 72 ; E: [128] stride 136
    __half* Vs = smh + FV_OFF;   // [128][72]
    __shared__ float psum[128];

    const int bh = blockIdx.y;
    const int b  = bh >> 4;
    const int h  = bh & 15;
    const int i0 = blockIdx.x * 128;
    const int tid  = threadIdx.x;
    const int lane = tid & 31;
    const int wid  = tid >> 5;
    const int wm   = (wid >> 1) * 32;
    const int wn   = (wid & 1) * 64;
    const int cn   = (wid & 1) * 32;

    const __half* qbase = g_q + (size_t)b * SEQ * DM + h * DEPTH;
    const __half* kbase = g_k + (size_t)b * SEQ * DM + h * DEPTH;
    const __half* vbase = g_v + (size_t)b * SEQ * DM + h * DEPTH;
    float* obase = attn + (size_t)bh * SEQ * SEQ;

    if (tid < 128) psum[tid] = 0.0f;

    // Load Q tile (pre-scaled by 0.125 at projection)
    const int lR = tid >> 3;          // 0..31
    const int lC = (tid & 7) * 8;     // 0..56
    #pragma unroll
    for (int p = 0; p < 4; ++p) {
        const int r = lR + p * 32;
        *(uint4*)&Qs[r * 72 + lC] =
            *(const uint4*)(qbase + (size_t)(i0 + r) * DM + lC);
    }

    wmma::fragment<wmma::accumulator, 16, 16, 16, float> cacc[2][2];
    #pragma unroll
    for (int i = 0; i < 2; ++i)
        #pragma unroll
        for (int j = 0; j < 2; ++j)
            wmma::fill_fragment(cacc[i][j], 0.0f);

    float lo[2] = {0.0f, 0.0f};
    float hi[2] = {0.0f, 0.0f};

    for (int jt = 0; jt < 16; ++jt) {
        const int j0 = jt * 128;

        __syncthreads();   // prev EV done: KE/Vs free
        #pragma unroll
        for (int p = 0; p < 4; ++p) {
            const int r = lR + p * 32;
            *(uint4*)&KE[r * 72 + lC] =
                *(const uint4*)(kbase + (size_t)(j0 + r) * DM + lC);
            *(uint4*)&Vs[r * 72 + lC] =
                *(const uint4*)(vbase + (size_t)(j0 + r) * DM + lC);
        }
        __syncthreads();

        // S = Q K^T  (warp 32x64, depth 64 = 4 k16-steps)
        wmma::fragment<wmma::accumulator, 16, 16, 16, float> sacc[2][4];
        #pragma unroll
        for (int i = 0; i < 2; ++i)
            #pragma unroll
            for (int j = 0; j < 4; ++j)
                wmma::fill_fragment(sacc[i][j], 0.0f);

        #pragma unroll
        for (int kk = 0; kk < DEPTH; kk += 16) {
            wmma::fragment<wmma::matrix_a, 16, 16, 16, __half,
                           wmma::row_major> af[2];
            wmma::fragment<wmma::matrix_b, 16, 16, 16, __half,
                           wmma::col_major> bf[4];
            #pragma unroll
            for (int i = 0; i < 2; ++i)
                wmma::load_matrix_sync(af[i], &Qs[(wm + i * 16) * 72 + kk], 72);
            #pragma unroll
            for (int j = 0; j < 4; ++j)
                wmma::load_matrix_sync(bf[j], &KE[(wn + j * 16) * 72 + kk], 72);
            #pragma unroll
            for (int i = 0; i < 2; ++i)
                #pragma unroll
                for (int j = 0; j < 4; ++j)
                    wmma::mma_sync(sacc[i][j], af[i], bf[j], sacc[i][j]);
        }

        // exp (fp32): attn gmem store + rowsums; keep for half E store
        #pragma unroll
        for (int i = 0; i < 2; ++i)
            #pragma unroll
            for (int j = 0; j < 4; ++j) {
                #pragma unroll
                for (int e = 0; e < 8; ++e) {
                    const float x = __expf(sacc[i][j].x[e]);
                    sacc[i][j].x[e] = x;
                    if ((e & 3) < 2) lo[i] += x; else hi[i] += x;
                }
                wmma::store_matrix_sync(
                    obase + (size_t)(i0 + wm + i * 16) * SEQ + j0 + wn + j * 16,
                    sacc[i][j], SEQ, wmma::mem_row_major);
            }

        __syncthreads();   // all warps done reading K from KE

        #pragma unroll
        for (int i = 0; i < 2; ++i)
            #pragma unroll
            for (int j = 0; j < 4; ++j)
                store_acc_half(&KE[(wm + i * 16) * 136 + wn + j * 16],
                               sacc[i][j].x, 136, lane, 1.0f, 1.0f);
        __syncthreads();   // E visible

        // ctx += E V  (warp 32x32, K=128 = 8 k16-steps)
        #pragma unroll
        for (int kk = 0; kk < 128; kk += 16) {
            wmma::fragment<wmma::matrix_a, 16, 16, 16, __half,
                           wmma::row_major> af[2];
            wmma::fragment<wmma::matrix_b, 16, 16, 16, __half,
                           wmma::row_major> bf[2];
            #pragma unroll
            for (int i = 0; i < 2; ++i)
                wmma::load_matrix_sync(af[i], &KE[(wm + i * 16) * 136 + kk], 136);
            #pragma unroll
            for (int j = 0; j < 2; ++j)
                wmma::load_matrix_sync(bf[j], &Vs[kk * 72 + cn + j * 16], 72);
            #pragma unroll
            for (int i = 0; i < 2; ++i)
                #pragma unroll
                for (int j = 0; j < 2; ++j)
                    wmma::mma_sync(cacc[i][j], af[i], bf[j], cacc[i][j]);
        }
    }

    // Deterministic rowsum -> rowinv
    #pragma unroll
    for (int i = 0; i < 2; ++i) {
        lo[i] += __shfl_xor_sync(0xffffffffu, lo[i], 1);
        lo[i] += __shfl_xor_sync(0xffffffffu, lo[i], 2);
        hi[i] += __shfl_xor_sync(0xffffffffu, hi[i], 1);
        hi[i] += __shfl_xor_sync(0xffffffffu, hi[i], 2);
    }
    __syncthreads();
    if ((lane & 3) == 0) {
        const int g = lane >> 2;
        #pragma unroll
        for (int i = 0; i < 2; ++i) {
            atomicAdd(&psum[wm + i * 16 + g],     lo[i]);
            atomicAdd(&psum[wm + i * 16 + 8 + g], hi[i]);
        }
    }
    __syncthreads();
    if (tid < 128) {
        const float inv = 1.0f / psum[tid];
        psum[tid] = inv;
        rowinv_g[(size_t)bh * SEQ + i0 + tid] = inv;
    }
    __syncthreads();

    // ctx scale + half store (feeds o_proj)
    const int g = lane >> 2;
    #pragma unroll
    for (int i = 0; i < 2; ++i) {
        const float ivlo = psum[wm + i * 16 + g];
        const float ivhi = psum[wm + i * 16 + 8 + g];
        #pragma unroll
        for (int j = 0; j < 2; ++j)
            store_acc_half(g_ctx + (size_t)(b * SEQ + i0 + wm + i * 16) * DM
                               + h * DEPTH + cn + j * 16,
                           cacc[i][j].x, DM, lane, ivlo, ivhi);
    }
}

// ---------------------------------------------------------------------------
// attn normalize in place: one block per attention row.
// ---------------------------------------------------------------------------
__global__ __launch_bounds__(256)
void attn_norm_kernel(float* __restrict__ attn, const float* __restrict__ rowinv)
{
    const float inv = rowinv[blockIdx.x];
    float4* p = (float4*)(attn + (size_t)blockIdx.x * SEQ);
    const int tid = threadIdx.x;
    float4 a = p[tid], b = p[tid + 256];
    a.x *= inv; a.y *= inv; a.z *= inv; a.w *= inv;
    b.x *= inv; b.y *= inv; b.z *= inv; b.w *= inv;
    p[tid] = a; p[tid + 256] = b;
}

// ---------------------------------------------------------------------------
extern "C" void kernel_launch(void* const* d_in, const int* in_sizes, int n_in,
                              void* d_out, int out_size)
{
    const float* query = (const float*)d_in[0];
    const float* key   = (const float*)d_in[1];
    const float* value = (const float*)d_in[2];
    const float* Wq = (const float*)d_in[3];
    const float* bq = (const float*)d_in[4];
    const float* Wk = (const float*)d_in[5];
    const float* bk = (const float*)d_in[6];
    const float* Wv = (const float*)d_in[7];
    const float* bv = (const float*)d_in[8];
    const float* Wo = (const float*)d_in[9];
    const float* bo = (const float*)d_in[10];

    float* out  = (float*)d_out;
    float* attn = out + (size_t)BATCH * SEQ * DM;

    float* rowinv;
    __half *rin, *rw;
    cudaGetSymbolAddress((void**)&rowinv, g_rowinv);
    cudaGetSymbolAddress((void**)&rin,    g_rin);
    cudaGetSymbolAddress((void**)&rw,     g_rw);

    static int init_done = 0;
    if (!init_done) {
        cudaFuncSetAttribute(attn_fused_fp16,
                             cudaFuncAttributeMaxDynamicSharedMemorySize,
                             FS_HALVES * 2);
        cudaFuncSetAttribute(qkv_proj_fp16,
                             cudaFuncAttributeMaxDynamicSharedMemorySize,
                             GE_SMEM_BYTES);
        cudaFuncSetAttribute(o_proj_fp16,
                             cudaFuncAttributeMaxDynamicSharedMemorySize,
                             GE_SMEM_BYTES);
        init_done = 1;
    }

    const int NIN = BATCH * SEQ * DM;   // 4M
    const int NW  = DM * DM;            // 1M

    f2h_kernel<<<512, 256>>>(query, rin + 0 * (size_t)NIN, NIN / 8);
    f2h_kernel<<<512, 256>>>(key,   rin + 1 * (size_t)NIN, NIN / 8);
    f2h_kernel<<<512, 256>>>(value, rin + 2 * (size_t)NIN, NIN / 8);
    f2h_kernel<<<256, 256>>>(Wq, rw + 0 * (size_t)NW, NW / 8);
    f2h_kernel<<<256, 256>>>(Wk, rw + 1 * (size_t)NW, NW / 8);
    f2h_kernel<<<256, 256>>>(Wv, rw + 2 * (size_t)NW, NW / 8);
    f2h_kernel<<<256, 256>>>(Wo, rw + 3 * (size_t)NW, NW / 8);

    dim3 gqkv(DM / 128, MROWS / 128, 3);   // (8, 32, 3)
    qkv_proj_fp16<<<gqkv, 256, GE_SMEM_BYTES>>>(bq, bk, bv);

    dim3 gatt(SEQ / 128, BATCH * NH);      // (16, 32)
    attn_fused_fp16<<<gatt, 256, FS_HALVES * 2>>>(attn, rowinv);

    attn_norm_kernel<<<NROWS, 256>>>(attn, rowinv);

    dim3 gproj(DM / 128, MROWS / 128);     // (8, 32)
    o_proj_fp16<<<gproj, 256, GE_SMEM_BYTES>>>(bo, out);
}

// round 10
// speedup vs baseline: 3.2008x; 1.0040x over previous
#include <cuda_runtime.h>
#include <cuda_fp16.h>
#include <mma.h>
#include <math.h>
#include <stdint.h>

using namespace nvcuda;

#define BATCH 2
#define SEQ   2048
#define DM    1024
#define NH    16
#define DEPTH 64
#define MROWS (BATCH * SEQ)       // 4096
#define NROWS (BATCH * NH * SEQ)  // 65536 attention rows

// Scratch (allocation-free rule: __device__ globals)
__device__ __half g_q[BATCH * SEQ * DM];
__device__ __half g_k[BATCH * SEQ * DM];
__device__ __half g_v[BATCH * SEQ * DM];
__device__ __half g_ctx[BATCH * SEQ * DM];
__device__ float  g_rowinv[NROWS];
__device__ __half g_rin[3][BATCH * SEQ * DM];   // fp16 inputs
__device__ __half g_rw[4][DM * DM];             // fp16 weights

__device__ __forceinline__ void cp_async16(void* smem, const void* gmem) {
    unsigned int s = (unsigned int)__cvta_generic_to_shared(smem);
    asm volatile("cp.async.cg.shared.global [%0], [%1], 16;\n" :: "r"(s), "l"(gmem));
}
__device__ __forceinline__ void cp_commit() {
    asm volatile("cp.async.commit_group;\n");
}
template <int N>
__device__ __forceinline__ void cp_wait() {
    asm volatile("cp.async.wait_group %0;\n" :: "n"(N));
}

// ---------------------------------------------------------------------------
// fp32 -> fp16 conversion (RN). n8 = n/8.
// ---------------------------------------------------------------------------
__global__ __launch_bounds__(256)
void f2h_kernel(const float* __restrict__ in, __half* __restrict__ out, int n8)
{
    const int stride = gridDim.x * 256;
    for (int i = blockIdx.x * 256 + threadIdx.x; i < n8; i += stride) {
        float4 a = ((const float4*)in)[2 * i];
        float4 b = ((const float4*)in)[2 * i + 1];
        __half2 h[4];
        h[0] = __floats2half2_rn(a.x, a.y);
        h[1] = __floats2half2_rn(a.z, a.w);
        h[2] = __floats2half2_rn(b.x, b.y);
        h[3] = __floats2half2_rn(b.z, b.w);
        ((uint2*)out)[2 * i]     = *(uint2*)&h[0];
        ((uint2*)out)[2 * i + 1] = *(uint2*)&h[2];
    }
}

// m16n16 f32 accumulator lane mapping (sm_80+ canonical):
//   lane = 4g+t; e0,e1,e4,e5 -> row g; e2,e3,e6,e7 -> row g+8
//   col = 2t + (e&1) + 8*(e>>2)
// Store acc as half to base[row*ldm + col] after adding rbias (per element).
__device__ __forceinline__
void store_acc_half(__half* base, const float* x, int ldm, int lane,
                    float slo, float shi)
{
    const int g = lane >> 2, t = lane & 3;
    __half2 p;
    p = __floats2half2_rn(x[0] * slo, x[1] * slo);
    *(__half2*)(base + (size_t)g * ldm + 2 * t) = p;
    p = __floats2half2_rn(x[2] * shi, x[3] * shi);
    *(__half2*)(base + (size_t)(g + 8) * ldm + 2 * t) = p;
    p = __floats2half2_rn(x[4] * slo, x[5] * slo);
    *(__half2*)(base + (size_t)g * ldm + 2 * t + 8) = p;
    p = __floats2half2_rn(x[6] * shi, x[7] * shi);
    *(__half2*)(base + (size_t)(g + 8) * ldm + 2 * t + 8) = p;
}

// ---------------------------------------------------------------------------
// FP16 GEMM + bias, cp.async 2-stage, block 128x128, BK=32, 256 thr,
// 8 warps (4m x 2n), warp 32x64.
// smem halves: A[2][128][40] | B[2][32][136] ; float bias[128] after.
// ---------------------------------------------------------------------------
#define GA(s,r,c)  smh[(s) * 5120 + (r) * 40 + (c)]
#define GB(s,r,c)  smh[10240 + (s) * 4352 + (r) * 136 + (c)]
#define GE_SMEM_BYTES (18944 * 2 + 128 * 4)

// OUT_HALF: write half with scale; else write float via store_matrix_sync.
template <bool OUT_HALF>
__device__ __forceinline__
void gemm_fp16_body(const __half* __restrict__ A, const __half* __restrict__ W,
                    const float* __restrict__ bias, void* __restrict__ C,
                    int K, int N, int bx, int by, float oscale)
{
    extern __shared__ __half smh[];
    float* sbias = (float*)(smh + 18944);

    const int tid  = threadIdx.x;
    const int lane = tid & 31;
    const int wid  = tid >> 5;
    const int brow = by * 128;
    const int bcol = bx * 128;
    const int wm   = (wid >> 1) * 32;
    const int wn   = (wid & 1) * 64;

    const int aRow = tid >> 2;            // 0..63
    const int aCol = (tid & 3) * 8;       // 0,8,16,24
    const int bRow = tid >> 4;            // 0..15
    const int bCol = (tid & 15) * 8;      // 0..120

    // Prefetch chunk 0
    #pragma unroll
    for (int p = 0; p < 2; ++p)
        cp_async16(&GA(0, aRow + p * 64, aCol),
                   A + (size_t)(brow + aRow + p * 64) * K + aCol);
    #pragma unroll
    for (int p = 0; p < 2; ++p)
        cp_async16(&GB(0, bRow + p * 16, bCol),
                   W + (size_t)(bRow + p * 16) * N + bcol + bCol);
    cp_commit();

    if (tid < 128) sbias[tid] = bias[bcol + tid];

    wmma::fragment<wmma::accumulator, 16, 16, 16, float> acc[2][4];
    #pragma unroll
    for (int i = 0; i < 2; ++i)
        #pragma unroll
        for (int j = 0; j < 4; ++j)
            wmma::fill_fragment(acc[i][j], 0.0f);

    const int NCH = K / 32;
    for (int c = 0; c < NCH; ++c) {
        if (c + 1 < NCH) {
            const int s = (c + 1) & 1;
            const int k0 = (c + 1) * 32;
            #pragma unroll
            for (int p = 0; p < 2; ++p)
                cp_async16(&GA(s, aRow + p * 64, aCol),
                           A + (size_t)(brow + aRow + p * 64) * K + k0 + aCol);
            #pragma unroll
            for (int p = 0; p < 2; ++p)
                cp_async16(&GB(s, bRow + p * 16, bCol),
                           W + (size_t)(k0 + bRow + p * 16) * N + bcol + bCol);
            cp_commit();
            cp_wait<1>();
        } else {
            cp_wait<0>();
        }
        __syncthreads();

        const int s = c & 1;
        #pragma unroll
        for (int kk = 0; kk < 32; kk += 16) {
            wmma::fragment<wmma::matrix_a, 16, 16, 16, __half,
                           wmma::row_major> af[2];
            wmma::fragment<wmma::matrix_b, 16, 16, 16, __half,
                           wmma::row_major> bf[4];
            #pragma unroll
            for (int i = 0; i < 2; ++i)
                wmma::load_matrix_sync(af[i], &GA(s, wm + i * 16, kk), 40);
            #pragma unroll
            for (int j = 0; j < 4; ++j)
                wmma::load_matrix_sync(bf[j], &GB(s, kk, wn + j * 16), 136);
            #pragma unroll
            for (int i = 0; i < 2; ++i)
                #pragma unroll
                for (int j = 0; j < 4; ++j)
                    wmma::mma_sync(acc[i][j], af[i], bf[j], acc[i][j]);
        }
        __syncthreads();
    }

    // Epilogue: add bias (mapping-based), then store.
    const int t = lane & 3;
    #pragma unroll
    for (int i = 0; i < 2; ++i)
        #pragma unroll
        for (int j = 0; j < 4; ++j) {
            const int cb = wn + j * 16 + 2 * t;
            const float b0 = sbias[cb],     b1 = sbias[cb + 1];
            const float b4 = sbias[cb + 8], b5 = sbias[cb + 9];
            acc[i][j].x[0] += b0; acc[i][j].x[1] += b1;
            acc[i][j].x[2] += b0; acc[i][j].x[3] += b1;
            acc[i][j].x[4] += b4; acc[i][j].x[5] += b5;
            acc[i][j].x[6] += b4; acc[i][j].x[7] += b5;
            if (OUT_HALF) {
                __half* out = (__half*)C;
                store_acc_half(out + (size_t)(brow + wm + i * 16) * N
                                   + bcol + wn + j * 16,
                               acc[i][j].x, N, lane, oscale, oscale);
            } else {
                wmma::store_matrix_sync(
                    (float*)C + (size_t)(brow + wm + i * 16) * N
                              + bcol + wn + j * 16,
                    acc[i][j], N, wmma::mem_row_major);
            }
        }
}

// QKV projections: z selects GEMM; q gets *0.125 folded in (exact for scores).
__global__ __launch_bounds__(256)
void qkv_proj_fp16(const float* __restrict__ bq, const float* __restrict__ bk,
                   const float* __restrict__ bv)
{
    const int z = blockIdx.z;
    const __half* A    = g_rin[z];
    const __half* W    = g_rw[z];
    const float* bias  = (z == 0) ? bq : (z == 1) ? bk : bv;
    __half*      C     = (z == 0) ? g_q : (z == 1) ? g_k : g_v;
    const float  scale = (z == 0) ? 0.125f : 1.0f;
    gemm_fp16_body<true>(A, W, bias, C, DM, DM, blockIdx.x, blockIdx.y, scale);
}

__global__ __launch_bounds__(256)
void o_proj_fp16(const float* __restrict__ bias, float* __restrict__ out)
{
    gemm_fp16_body<false>(g_ctx, g_rw[3], bias, out, DM, DM,
                          blockIdx.x, blockIdx.y, 1.0f);
}

// ---------------------------------------------------------------------------
// Fused attention (fp16 operands, fp32 accum). Per block = (bh, 128 q-rows).
// 16 key tiles: S = Qs K^T (Q pre-scaled) -> raw fp32 exp -> attn gmem +
// rowsums; half E -> smem; ctx += E V. End: rowinv, scaled half ctx store.
// smem halves: Qs[128][72] | KE[128][136] (K stride 72 alias, then E) |
//              Vs[128][72]  = 71680 B
// ---------------------------------------------------------------------------
#define FQ_OFF  0
#define FK_OFF  9216
#define FV_OFF  (9216 + 17408)
#define FS_HALVES (9216 + 17408 + 9216)

__global__ __launch_bounds__(256)
void attn_fused_fp16(float* __restrict__ attn, float* __restrict__ rowinv_g)
{
    extern __shared__ __half smh[];
    __half* Qs = smh + FQ_OFF;   // [128][72]
    __half* KE = smh + FK_OFF;   // K: [128] stride 72 ; E: [128] stride 136
    __half* Vs = smh + FV_OFF;   // [128][72]
    __shared__ float psum[128];

    const int bh = blockIdx.y;
    const int b  = bh >> 4;
    const int h  = bh & 15;
    const int i0 = blockIdx.x * 128;
    const int tid  = threadIdx.x;
    const int lane = tid & 31;
    const int wid  = tid >> 5;
    const int wm   = (wid >> 1) * 32;
    const int wn   = (wid & 1) * 64;
    const int cn   = (wid & 1) * 32;

    const __half* qbase = g_q + (size_t)b * SEQ * DM + h * DEPTH;
    const __half* kbase = g_k + (size_t)b * SEQ * DM + h * DEPTH;
    const __half* vbase = g_v + (size_t)b * SEQ * DM + h * DEPTH;
    float* obase = attn + (size_t)bh * SEQ * SEQ;

    if (tid < 128) psum[tid] = 0.0f;

    // Load Q tile (pre-scaled by 0.125 at projection)
    const int lR = tid >> 3;          // 0..31
    const int lC = (tid & 7) * 8;     // 0..56
    #pragma unroll
    for (int p = 0; p < 4; ++p) {
        const int r = lR + p * 32;
        *(uint4*)&Qs[r * 72 + lC] =
            *(const uint4*)(qbase + (size_t)(i0 + r) * DM + lC);
    }

    wmma::fragment<wmma::accumulator, 16, 16, 16, float> cacc[2][2];
    #pragma unroll
    for (int i = 0; i < 2; ++i)
        #pragma unroll
        for (int j = 0; j < 2; ++j)
            wmma::fill_fragment(cacc[i][j], 0.0f);

    float lo[2] = {0.0f, 0.0f};
    float hi[2] = {0.0f, 0.0f};

    for (int jt = 0; jt < 16; ++jt) {
        const int j0 = jt * 128;

        __syncthreads();   // prev EV done: KE/Vs free
        #pragma unroll
        for (int p = 0; p < 4; ++p) {
            const int r = lR + p * 32;
            *(uint4*)&KE[r * 72 + lC] =
                *(const uint4*)(kbase + (size_t)(j0 + r) * DM + lC);
            *(uint4*)&Vs[r * 72 + lC] =
                *(const uint4*)(vbase + (size_t)(j0 + r) * DM + lC);
        }
        __syncthreads();

        // S = Q K^T  (warp 32x64, depth 64 = 4 k16-steps)
        wmma::fragment<wmma::accumulator, 16, 16, 16, float> sacc[2][4];
        #pragma unroll
        for (int i = 0; i < 2; ++i)
            #pragma unroll
            for (int j = 0; j < 4; ++j)
                wmma::fill_fragment(sacc[i][j], 0.0f);

        #pragma unroll
        for (int kk = 0; kk < DEPTH; kk += 16) {
            wmma::fragment<wmma::matrix_a, 16, 16, 16, __half,
                           wmma::row_major> af[2];
            wmma::fragment<wmma::matrix_b, 16, 16, 16, __half,
                           wmma::col_major> bf[4];
            #pragma unroll
            for (int i = 0; i < 2; ++i)
                wmma::load_matrix_sync(af[i], &Qs[(wm + i * 16) * 72 + kk], 72);
            #pragma unroll
            for (int j = 0; j < 4; ++j)
                wmma::load_matrix_sync(bf[j], &KE[(wn + j * 16) * 72 + kk], 72);
            #pragma unroll
            for (int i = 0; i < 2; ++i)
                #pragma unroll
                for (int j = 0; j < 4; ++j)
                    wmma::mma_sync(sacc[i][j], af[i], bf[j], sacc[i][j]);
        }

        // exp (fp32): attn gmem store + rowsums; keep for half E store
        #pragma unroll
        for (int i = 0; i < 2; ++i)
            #pragma unroll
            for (int j = 0; j < 4; ++j) {
                #pragma unroll
                for (int e = 0; e < 8; ++e) {
                    const float x = __expf(sacc[i][j].x[e]);
                    sacc[i][j].x[e] = x;
                    if ((e & 3) < 2) lo[i] += x; else hi[i] += x;
                }
                wmma::store_matrix_sync(
                    obase + (size_t)(i0 + wm + i * 16) * SEQ + j0 + wn + j * 16,
                    sacc[i][j], SEQ, wmma::mem_row_major);
            }

        __syncthreads();   // all warps done reading K from KE

        #pragma unroll
        for (int i = 0; i < 2; ++i)
            #pragma unroll
            for (int j = 0; j < 4; ++j)
                store_acc_half(&KE[(wm + i * 16) * 136 + wn + j * 16],
                               sacc[i][j].x, 136, lane, 1.0f, 1.0f);
        __syncthreads();   // E visible

        // ctx += E V  (warp 32x32, K=128 = 8 k16-steps)
        #pragma unroll
        for (int kk = 0; kk < 128; kk += 16) {
            wmma::fragment<wmma::matrix_a, 16, 16, 16, __half,
                           wmma::row_major> af[2];
            wmma::fragment<wmma::matrix_b, 16, 16, 16, __half,
                           wmma::row_major> bf[2];
            #pragma unroll
            for (int i = 0; i < 2; ++i)
                wmma::load_matrix_sync(af[i], &KE[(wm + i * 16) * 136 + kk], 136);
            #pragma unroll
            for (int j = 0; j < 2; ++j)
                wmma::load_matrix_sync(bf[j], &Vs[kk * 72 + cn + j * 16], 72);
            #pragma unroll
            for (int i = 0; i < 2; ++i)
                #pragma unroll
                for (int j = 0; j < 2; ++j)
                    wmma::mma_sync(cacc[i][j], af[i], bf[j], cacc[i][j]);
        }
    }

    // Deterministic rowsum -> rowinv
    #pragma unroll
    for (int i = 0; i < 2; ++i) {
        lo[i] += __shfl_xor_sync(0xffffffffu, lo[i], 1);
        lo[i] += __shfl_xor_sync(0xffffffffu, lo[i], 2);
        hi[i] += __shfl_xor_sync(0xffffffffu, hi[i], 1);
        hi[i] += __shfl_xor_sync(0xffffffffu, hi[i], 2);
    }
    __syncthreads();
    if ((lane & 3) == 0) {
        const int g = lane >> 2;
        #pragma unroll
        for (int i = 0; i < 2; ++i) {
            atomicAdd(&psum[wm + i * 16 + g],     lo[i]);
            atomicAdd(&psum[wm + i * 16 + 8 + g], hi[i]);
        }
    }
    __syncthreads();
    if (tid < 128) {
        const float inv = 1.0f / psum[tid];
        psum[tid] = inv;
        rowinv_g[(size_t)bh * SEQ + i0 + tid] = inv;
    }
    __syncthreads();

    // ctx scale + half store (feeds o_proj)
    const int g = lane >> 2;
    #pragma unroll
    for (int i = 0; i < 2; ++i) {
        const float ivlo = psum[wm + i * 16 + g];
        const float ivhi = psum[wm + i * 16 + 8 + g];
        #pragma unroll
        for (int j = 0; j < 2; ++j)
            store_acc_half(g_ctx + (size_t)(b * SEQ + i0 + wm + i * 16) * DM
                               + h * DEPTH + cn + j * 16,
                           cacc[i][j].x, DM, lane, ivlo, ivhi);
    }
}

// ---------------------------------------------------------------------------
// attn normalize in place: one block per attention row.
// ---------------------------------------------------------------------------
__global__ __launch_bounds__(256)
void attn_norm_kernel(float* __restrict__ attn, const float* __restrict__ rowinv)
{
    const float inv = rowinv[blockIdx.x];
    float4* p = (float4*)(attn + (size_t)blockIdx.x * SEQ);
    const int tid = threadIdx.x;
    float4 a = p[tid], b = p[tid + 256];
    a.x *= inv; a.y *= inv; a.z *= inv; a.w *= inv;
    b.x *= inv; b.y *= inv; b.z *= inv; b.w *= inv;
    p[tid] = a; p[tid + 256] = b;
}

// ---------------------------------------------------------------------------
extern "C" void kernel_launch(void* const* d_in, const int* in_sizes, int n_in,
                              void* d_out, int out_size)
{
    const float* query = (const float*)d_in[0];
    const float* key   = (const float*)d_in[1];
    const float* value = (const float*)d_in[2];
    const float* Wq = (const float*)d_in[3];
    const float* bq = (const float*)d_in[4];
    const float* Wk = (const float*)d_in[5];
    const float* bk = (const float*)d_in[6];
    const float* Wv = (const float*)d_in[7];
    const float* bv = (const float*)d_in[8];
    const float* Wo = (const float*)d_in[9];
    const float* bo = (const float*)d_in[10];

    float* out  = (float*)d_out;
    float* attn = out + (size_t)BATCH * SEQ * DM;

    float* rowinv;
    __half *rin, *rw;
    cudaGetSymbolAddress((void**)&rowinv, g_rowinv);
    cudaGetSymbolAddress((void**)&rin,    g_rin);
    cudaGetSymbolAddress((void**)&rw,     g_rw);

    static int init_done = 0;
    if (!init_done) {
        cudaFuncSetAttribute(attn_fused_fp16,
                             cudaFuncAttributeMaxDynamicSharedMemorySize,
                             FS_HALVES * 2);
        cudaFuncSetAttribute(qkv_proj_fp16,
                             cudaFuncAttributeMaxDynamicSharedMemorySize,
                             GE_SMEM_BYTES);
        cudaFuncSetAttribute(o_proj_fp16,
                             cudaFuncAttributeMaxDynamicSharedMemorySize,
                             GE_SMEM_BYTES);
        init_done = 1;
    }

    const int NIN = BATCH * SEQ * DM;   // 4M
    const int NW  = DM * DM;            // 1M

    f2h_kernel<<<512, 256>>>(query, rin + 0 * (size_t)NIN, NIN / 8);
    f2h_kernel<<<512, 256>>>(key,   rin + 1 * (size_t)NIN, NIN / 8);
    f2h_kernel<<<512, 256>>>(value, rin + 2 * (size_t)NIN, NIN / 8);
    f2h_kernel<<<256, 256>>>(Wq, rw + 0 * (size_t)NW, NW / 8);
    f2h_kernel<<<256, 256>>>(Wk, rw + 1 * (size_t)NW, NW / 8);
    f2h_kernel<<<256, 256>>>(Wv, rw + 2 * (size_t)NW, NW / 8);
    f2h_kernel<<<256, 256>>>(Wo, rw + 3 * (size_t)NW, NW / 8);

    dim3 gqkv(DM / 128, MROWS / 128, 3);   // (8, 32, 3)
    qkv_proj_fp16<<<gqkv, 256, GE_SMEM_BYTES>>>(bq, bk, bv);

    dim3 gatt(SEQ / 128, BATCH * NH);      // (16, 32)
    attn_fused_fp16<<<gatt, 256, FS_HALVES * 2>>>(attn, rowinv);

    attn_norm_kernel<<<NROWS, 256>>>(attn, rowinv);

    dim3 gproj(DM / 128, MROWS / 128);     // (8, 32)
    o_proj_fp16<<<gproj, 256, GE_SMEM_BYTES>>>(bo, out);
}

// round 14
// speedup vs baseline: 3.9566x; 1.2361x over previous
#include <cuda_runtime.h>
#include <cuda_fp16.h>
#include <mma.h>
#include <math.h>
#include <stdint.h>

using namespace nvcuda;

#define BATCH 2
#define SEQ   2048
#define DM    1024
#define NH    16
#define DEPTH 64
#define MROWS (BATCH * SEQ)       // 4096
#define NROWS (BATCH * NH * SEQ)  // 65536 attention rows

// Scratch (allocation-free rule: __device__ globals)
__device__ __half g_q[BATCH * SEQ * DM];
__device__ __half g_k[BATCH * SEQ * DM];
__device__ __half g_v[BATCH * SEQ * DM];
__device__ __half g_ctx[BATCH * SEQ * DM];
__device__ float  g_rowinv[NROWS];
__device__ __half g_rin[3][BATCH * SEQ * DM];   // fp16 inputs
__device__ __half g_rw[4][DM * DM];             // fp16 weights

__device__ __forceinline__ void cp_async16(void* smem, const void* gmem) {
    unsigned int s = (unsigned int)__cvta_generic_to_shared(smem);
    asm volatile("cp.async.cg.shared.global [%0], [%1], 16;\n" :: "r"(s), "l"(gmem));
}
__device__ __forceinline__ void cp_commit() {
    asm volatile("cp.async.commit_group;\n");
}
template <int N>
__device__ __forceinline__ void cp_wait() {
    asm volatile("cp.async.wait_group %0;\n" :: "n"(N));
}

// ---------------------------------------------------------------------------
// fp32 -> fp16 conversion (RN). n8 = n/8.
// ---------------------------------------------------------------------------
__global__ __launch_bounds__(256)
void f2h_kernel(const float* __restrict__ in, __half* __restrict__ out, int n8)
{
    const int stride = gridDim.x * 256;
    for (int i = blockIdx.x * 256 + threadIdx.x; i < n8; i += stride) {
        float4 a = ((const float4*)in)[2 * i];
        float4 b = ((const float4*)in)[2 * i + 1];
        __half2 h[4];
        h[0] = __floats2half2_rn(a.x, a.y);
        h[1] = __floats2half2_rn(a.z, a.w);
        h[2] = __floats2half2_rn(b.x, b.y);
        h[3] = __floats2half2_rn(b.z, b.w);
        ((uint2*)out)[2 * i]     = *(uint2*)&h[0];
        ((uint2*)out)[2 * i + 1] = *(uint2*)&h[2];
    }
}

// m16n16 f32 accumulator lane mapping (sm_80+ canonical):
//   lane = 4g+t; e0,e1,e4,e5 -> row g; e2,e3,e6,e7 -> row g+8
//   col = 2t + (e&1) + 8*(e>>2)
__device__ __forceinline__
void store_acc_half(__half* base, const float* x, int ldm, int lane,
                    float slo, float shi)
{
    const int g = lane >> 2, t = lane & 3;
    __half2 p;
    p = __floats2half2_rn(x[0] * slo, x[1] * slo);
    *(__half2*)(base + (size_t)g * ldm + 2 * t) = p;
    p = __floats2half2_rn(x[2] * shi, x[3] * shi);
    *(__half2*)(base + (size_t)(g + 8) * ldm + 2 * t) = p;
    p = __floats2half2_rn(x[4] * slo, x[5] * slo);
    *(__half2*)(base + (size_t)g * ldm + 2 * t + 8) = p;
    p = __floats2half2_rn(x[6] * shi, x[7] * shi);
    *(__half2*)(base + (size_t)(g + 8) * ldm + 2 * t + 8) = p;
}

// ---------------------------------------------------------------------------
// FP16 GEMM + bias, cp.async 2-stage, block 128x128, BK=32, 256 thr,
// 8 warps (4m x 2n), warp 32x64.
// ---------------------------------------------------------------------------
#define GA(s,r,c)  smh[(s) * 5120 + (r) * 40 + (c)]
#define GB(s,r,c)  smh[10240 + (s) * 4352 + (r) * 136 + (c)]
#define GE_SMEM_BYTES (18944 * 2 + 128 * 4)

template <bool OUT_HALF>
__device__ __forceinline__
void gemm_fp16_body(const __half* __restrict__ A, const __half* __restrict__ W,
                    const float* __restrict__ bias, void* __restrict__ C,
                    int K, int N, int bx, int by, float oscale)
{
    extern __shared__ __half smh[];
    float* sbias = (float*)(smh + 18944);

    const int tid  = threadIdx.x;
    const int lane = tid & 31;
    const int wid  = tid >> 5;
    const int brow = by * 128;
    const int bcol = bx * 128;
    const int wm   = (wid >> 1) * 32;
    const int wn   = (wid & 1) * 64;

    const int aRow = tid >> 2;            // 0..63
    const int aCol = (tid & 3) * 8;       // 0,8,16,24
    const int bRow = tid >> 4;            // 0..15
    const int bCol = (tid & 15) * 8;      // 0..120

    #pragma unroll
    for (int p = 0; p < 2; ++p)
        cp_async16(&GA(0, aRow + p * 64, aCol),
                   A + (size_t)(brow + aRow + p * 64) * K + aCol);
    #pragma unroll
    for (int p = 0; p < 2; ++p)
        cp_async16(&GB(0, bRow + p * 16, bCol),
                   W + (size_t)(bRow + p * 16) * N + bcol + bCol);
    cp_commit();

    if (tid < 128) sbias[tid] = bias[bcol + tid];

    wmma::fragment<wmma::accumulator, 16, 16, 16, float> acc[2][4];
    #pragma unroll
    for (int i = 0; i < 2; ++i)
        #pragma unroll
        for (int j = 0; j < 4; ++j)
            wmma::fill_fragment(acc[i][j], 0.0f);

    const int NCH = K / 32;
    for (int c = 0; c < NCH; ++c) {
        if (c + 1 < NCH) {
            const int s = (c + 1) & 1;
            const int k0 = (c + 1) * 32;
            #pragma unroll
            for (int p = 0; p < 2; ++p)
                cp_async16(&GA(s, aRow + p * 64, aCol),
                           A + (size_t)(brow + aRow + p * 64) * K + k0 + aCol);
            #pragma unroll
            for (int p = 0; p < 2; ++p)
                cp_async16(&GB(s, bRow + p * 16, bCol),
                           W + (size_t)(k0 + bRow + p * 16) * N + bcol + bCol);
            cp_commit();
            cp_wait<1>();
        } else {
            cp_wait<0>();
        }
        __syncthreads();

        const int s = c & 1;
        #pragma unroll
        for (int kk = 0; kk < 32; kk += 16) {
            wmma::fragment<wmma::matrix_a, 16, 16, 16, __half,
                           wmma::row_major> af[2];
            wmma::fragment<wmma::matrix_b, 16, 16, 16, __half,
                           wmma::row_major> bf[4];
            #pragma unroll
            for (int i = 0; i < 2; ++i)
                wmma::load_matrix_sync(af[i], &GA(s, wm + i * 16, kk), 40);
            #pragma unroll
            for (int j = 0; j < 4; ++j)
                wmma::load_matrix_sync(bf[j], &GB(s, kk, wn + j * 16), 136);
            #pragma unroll
            for (int i = 0; i < 2; ++i)
                #pragma unroll
                for (int j = 0; j < 4; ++j)
                    wmma::mma_sync(acc[i][j], af[i], bf[j], acc[i][j]);
        }
        __syncthreads();
    }

    const int t = lane & 3;
    #pragma unroll
    for (int i = 0; i < 2; ++i)
        #pragma unroll
        for (int j = 0; j < 4; ++j) {
            const int cb = wn + j * 16 + 2 * t;
            const float b0 = sbias[cb],     b1 = sbias[cb + 1];
            const float b4 = sbias[cb + 8], b5 = sbias[cb + 9];
            acc[i][j].x[0] += b0; acc[i][j].x[1] += b1;
            acc[i][j].x[2] += b0; acc[i][j].x[3] += b1;
            acc[i][j].x[4] += b4; acc[i][j].x[5] += b5;
            acc[i][j].x[6] += b4; acc[i][j].x[7] += b5;
            if (OUT_HALF) {
                __half* out = (__half*)C;
                store_acc_half(out + (size_t)(brow + wm + i * 16) * N
                                   + bcol + wn + j * 16,
                               acc[i][j].x, N, lane, oscale, oscale);
            } else {
                wmma::store_matrix_sync(
                    (float*)C + (size_t)(brow + wm + i * 16) * N
                              + bcol + wn + j * 16,
                    acc[i][j], N, wmma::mem_row_major);
            }
        }
}

__global__ __launch_bounds__(256)
void qkv_proj_fp16(const float* __restrict__ bq, const float* __restrict__ bk,
                   const float* __restrict__ bv)
{
    const int z = blockIdx.z;
    const __half* A    = g_rin[z];
    const __half* W    = g_rw[z];
    const float* bias  = (z == 0) ? bq : (z == 1) ? bk : bv;
    __half*      C     = (z == 0) ? g_q : (z == 1) ? g_k : g_v;
    const float  scale = (z == 0) ? 0.125f : 1.0f;
    gemm_fp16_body<true>(A, W, bias, C, DM, DM, blockIdx.x, blockIdx.y, scale);
}

__global__ __launch_bounds__(256)
void o_proj_fp16(const float* __restrict__ bias, float* __restrict__ out)
{
    gemm_fp16_body<false>(g_ctx, g_rw[3], bias, out, DM, DM,
                          blockIdx.x, blockIdx.y, 1.0f);
}

// ---------------------------------------------------------------------------
// Fused attention pass A: NO attn gmem writes. Per block = (bh, 128 q-rows).
// 16 key tiles: S = Qs K^T -> exp (fp32, rowsums) -> half E smem -> ctx += EV.
// End: rowinv computed + stored; ctx scaled, half store.
// smem halves: Qs[128][72] | KE[128][136] | Vs[128][72] = 71680 B
// ---------------------------------------------------------------------------
#define FQ_OFF  0
#define FK_OFF  9216
#define FV_OFF  (9216 + 17408)
#define FS_HALVES (9216 + 17408 + 9216)

__global__ __launch_bounds__(256)
void attn_fused_fp16(float* __restrict__ rowinv_g)
{
    extern __shared__ __half smh[];
    __half* Qs = smh + FQ_OFF;   // [128][72]
    __half* KE = smh + FK_OFF;   // K: [128] stride 72 ; E: [128] stride 136
    __half* Vs = smh + FV_OFF;   // [128][72]
    __shared__ float psum[128];

    const int bh = blockIdx.y;
    const int b  = bh >> 4;
    const int h  = bh & 15;
    const int i0 = blockIdx.x * 128;
    const int tid  = threadIdx.x;
    const int lane = tid & 31;
    const int wid  = tid >> 5;
    const int wm   = (wid >> 1) * 32;
    const int wn   = (wid & 1) * 64;
    const int cn   = (wid & 1) * 32;

    const __half* qbase = g_q + (size_t)b * SEQ * DM + h * DEPTH;
    const __half* kbase = g_k + (size_t)b * SEQ * DM + h * DEPTH;
    const __half* vbase = g_v + (size_t)b * SEQ * DM + h * DEPTH;

    if (tid < 128) psum[tid] = 0.0f;

    const int lR = tid >> 3;          // 0..31
    const int lC = (tid & 7) * 8;     // 0..56
    #pragma unroll
    for (int p = 0; p < 4; ++p) {
        const int r = lR + p * 32;
        *(uint4*)&Qs[r * 72 + lC] =
            *(const uint4*)(qbase + (size_t)(i0 + r) * DM + lC);
    }

    wmma::fragment<wmma::accumulator, 16, 16, 16, float> cacc[2][2];
    #pragma unroll
    for (int i = 0; i < 2; ++i)
        #pragma unroll
        for (int j = 0; j < 2; ++j)
            wmma::fill_fragment(cacc[i][j], 0.0f);

    float lo[2] = {0.0f, 0.0f};
    float hi[2] = {0.0f, 0.0f};

    for (int jt = 0; jt < 16; ++jt) {
        const int j0 = jt * 128;

        __syncthreads();   // prev EV done: KE/Vs free
        #pragma unroll
        for (int p = 0; p < 4; ++p) {
            const int r = lR + p * 32;
            *(uint4*)&KE[r * 72 + lC] =
                *(const uint4*)(kbase + (size_t)(j0 + r) * DM + lC);
            *(uint4*)&Vs[r * 72 + lC] =
                *(const uint4*)(vbase + (size_t)(j0 + r) * DM + lC);
        }
        __syncthreads();

        wmma::fragment<wmma::accumulator, 16, 16, 16, float> sacc[2][4];
        #pragma unroll
        for (int i = 0; i < 2; ++i)
            #pragma unroll
            for (int j = 0; j < 4; ++j)
                wmma::fill_fragment(sacc[i][j], 0.0f);

        #pragma unroll
        for (int kk = 0; kk < DEPTH; kk += 16) {
            wmma::fragment<wmma::matrix_a, 16, 16, 16, __half,
                           wmma::row_major> af[2];
            wmma::fragment<wmma::matrix_b, 16, 16, 16, __half,
                           wmma::col_major> bf[4];
            #pragma unroll
            for (int i = 0; i < 2; ++i)
                wmma::load_matrix_sync(af[i], &Qs[(wm + i * 16) * 72 + kk], 72);
            #pragma unroll
            for (int j = 0; j < 4; ++j)
                wmma::load_matrix_sync(bf[j], &KE[(wn + j * 16) * 72 + kk], 72);
            #pragma unroll
            for (int i = 0; i < 2; ++i)
                #pragma unroll
                for (int j = 0; j < 4; ++j)
                    wmma::mma_sync(sacc[i][j], af[i], bf[j], sacc[i][j]);
        }

        // exp (fp32) + rowsums (no gmem store)
        #pragma unroll
        for (int i = 0; i < 2; ++i)
            #pragma unroll
            for (int j = 0; j < 4; ++j)
                #pragma unroll
                for (int e = 0; e < 8; ++e) {
                    const float x = __expf(sacc[i][j].x[e]);
                    sacc[i][j].x[e] = x;
                    if ((e & 3) < 2) lo[i] += x; else hi[i] += x;
                }

        __syncthreads();   // all warps done reading K from KE

        #pragma unroll
        for (int i = 0; i < 2; ++i)
            #pragma unroll
            for (int j = 0; j < 4; ++j)
                store_acc_half(&KE[(wm + i * 16) * 136 + wn + j * 16],
                               sacc[i][j].x, 136, lane, 1.0f, 1.0f);
        __syncthreads();   // E visible

        #pragma unroll
        for (int kk = 0; kk < 128; kk += 16) {
            wmma::fragment<wmma::matrix_a, 16, 16, 16, __half,
                           wmma::row_major> af[2];
            wmma::fragment<wmma::matrix_b, 16, 16, 16, __half,
                           wmma::row_major> bf[2];
            #pragma unroll
            for (int i = 0; i < 2; ++i)
                wmma::load_matrix_sync(af[i], &KE[(wm + i * 16) * 136 + kk], 136);
            #pragma unroll
            for (int j = 0; j < 2; ++j)
                wmma::load_matrix_sync(bf[j], &Vs[kk * 72 + cn + j * 16], 72);
            #pragma unroll
            for (int i = 0; i < 2; ++i)
                #pragma unroll
                for (int j = 0; j < 2; ++j)
                    wmma::mma_sync(cacc[i][j], af[i], bf[j], cacc[i][j]);
        }
    }

    // Deterministic rowsum -> rowinv
    #pragma unroll
    for (int i = 0; i < 2; ++i) {
        lo[i] += __shfl_xor_sync(0xffffffffu, lo[i], 1);
        lo[i] += __shfl_xor_sync(0xffffffffu, lo[i], 2);
        hi[i] += __shfl_xor_sync(0xffffffffu, hi[i], 1);
        hi[i] += __shfl_xor_sync(0xffffffffu, hi[i], 2);
    }
    __syncthreads();
    if ((lane & 3) == 0) {
        const int g = lane >> 2;
        #pragma unroll
        for (int i = 0; i < 2; ++i) {
            atomicAdd(&psum[wm + i * 16 + g],     lo[i]);
            atomicAdd(&psum[wm + i * 16 + 8 + g], hi[i]);
        }
    }
    __syncthreads();
    if (tid < 128) {
        const float inv = 1.0f / psum[tid];
        psum[tid] = inv;
        rowinv_g[(size_t)bh * SEQ + i0 + tid] = inv;
    }
    __syncthreads();

    const int g = lane >> 2;
    #pragma unroll
    for (int i = 0; i < 2; ++i) {
        const float ivlo = psum[wm + i * 16 + g];
        const float ivhi = psum[wm + i * 16 + 8 + g];
        #pragma unroll
        for (int j = 0; j < 2; ++j)
            store_acc_half(g_ctx + (size_t)(b * SEQ + i0 + wm + i * 16) * DM
                               + h * DEPTH + cn + j * 16,
                           cacc[i][j].x, DM, lane, ivlo, ivhi);
    }
}

// ---------------------------------------------------------------------------
// Pass B: scores replay. Recompute S = Q K^T (identical MMAs), write
// attn = __expf(S) * rowinv ONCE, fp32, streaming stores.
// Per block = (bh, 128 q-rows), loop 16 j-tiles.
// ---------------------------------------------------------------------------
__global__ __launch_bounds__(256)
void attn_write_fp16(float* __restrict__ attn, const float* __restrict__ rowinv)
{
    __shared__ __half Qs[128 * 72];
    __shared__ __half Ks[128 * 72];
    __shared__ float invs[128];

    const int bh = blockIdx.y;
    const int b  = bh >> 4;
    const int h  = bh & 15;
    const int i0 = blockIdx.x * 128;
    const int tid  = threadIdx.x;
    const int lane = tid & 31;
    const int wid  = tid >> 5;
    const int wm   = (wid >> 1) * 32;
    const int wn   = (wid & 1) * 64;

    const __half* qbase = g_q + (size_t)b * SEQ * DM + h * DEPTH;
    const __half* kbase = g_k + (size_t)b * SEQ * DM + h * DEPTH;
    float* obase = attn + (size_t)bh * SEQ * SEQ;

    const int lR = tid >> 3;          // 0..31
    const int lC = (tid & 7) * 8;     // 0..56
    #pragma unroll
    for (int p = 0; p < 4; ++p) {
        const int r = lR + p * 32;
        *(uint4*)&Qs[r * 72 + lC] =
            *(const uint4*)(qbase + (size_t)(i0 + r) * DM + lC);
    }
    if (tid < 128) invs[tid] = rowinv[(size_t)bh * SEQ + i0 + tid];

    const int g = lane >> 2, t = lane & 3;

    for (int jt = 0; jt < 16; ++jt) {
        const int j0 = jt * 128;

        __syncthreads();   // prev epilogue done reading Ks
        #pragma unroll
        for (int p = 0; p < 4; ++p) {
            const int r = lR + p * 32;
            *(uint4*)&Ks[r * 72 + lC] =
                *(const uint4*)(kbase + (size_t)(j0 + r) * DM + lC);
        }
        __syncthreads();

        wmma::fragment<wmma::accumulator, 16, 16, 16, float> sacc[2][4];
        #pragma unroll
        for (int i = 0; i < 2; ++i)
            #pragma unroll
            for (int j = 0; j < 4; ++j)
                wmma::fill_fragment(sacc[i][j], 0.0f);

        #pragma unroll
        for (int kk = 0; kk < DEPTH; kk += 16) {
            wmma::fragment<wmma::matrix_a, 16, 16, 16, __half,
                           wmma::row_major> af[2];
            wmma::fragment<wmma::matrix_b, 16, 16, 16, __half,
                           wmma::col_major> bf[4];
            #pragma unroll
            for (int i = 0; i < 2; ++i)
                wmma::load_matrix_sync(af[i], &Qs[(wm + i * 16) * 72 + kk], 72);
            #pragma unroll
            for (int j = 0; j < 4; ++j)
                wmma::load_matrix_sync(bf[j], &Ks[(wn + j * 16) * 72 + kk], 72);
            #pragma unroll
            for (int i = 0; i < 2; ++i)
                #pragma unroll
                for (int j = 0; j < 4; ++j)
                    wmma::mma_sync(sacc[i][j], af[i], bf[j], sacc[i][j]);
        }

        // attn = exp(S) * rowinv, streaming fp32 stores (mapping-based)
        #pragma unroll
        for (int i = 0; i < 2; ++i) {
            const float ivlo = invs[wm + i * 16 + g];
            const float ivhi = invs[wm + i * 16 + 8 + g];
            #pragma unroll
            for (int j = 0; j < 4; ++j) {
                float* base = obase + (size_t)(i0 + wm + i * 16) * SEQ
                            + j0 + wn + j * 16;
                const float* x = sacc[i][j].x;
                float2 v;
                v.x = __expf(x[0]) * ivlo; v.y = __expf(x[1]) * ivlo;
                __stcs((float2*)(base + (size_t)g * SEQ + 2 * t), v);
                v.x = __expf(x[2]) * ivhi; v.y = __expf(x[3]) * ivhi;
                __stcs((float2*)(base + (size_t)(g + 8) * SEQ + 2 * t), v);
                v.x = __expf(x[4]) * ivlo; v.y = __expf(x[5]) * ivlo;
                __stcs((float2*)(base + (size_t)g * SEQ + 2 * t + 8), v);
                v.x = __expf(x[6]) * ivhi; v.y = __expf(x[7]) * ivhi;
                __stcs((float2*)(base + (size_t)(g + 8) * SEQ + 2 * t + 8), v);
            }
        }
    }
}

// ---------------------------------------------------------------------------
extern "C" void kernel_launch(void* const* d_in, const int* in_sizes, int n_in,
                              void* d_out, int out_size)
{
    const float* query = (const float*)d_in[0];
    const float* key   = (const float*)d_in[1];
    const float* value = (const float*)d_in[2];
    const float* Wq = (const float*)d_in[3];
    const float* bq = (const float*)d_in[4];
    const float* Wk = (const float*)d_in[5];
    const float* bk = (const float*)d_in[6];
    const float* Wv = (const float*)d_in[7];
    const float* bv = (const float*)d_in[8];
    const float* Wo = (const float*)d_in[9];
    const float* bo = (const float*)d_in[10];

    float* out  = (float*)d_out;
    float* attn = out + (size_t)BATCH * SEQ * DM;

    float* rowinv;
    __half *rin, *rw;
    cudaGetSymbolAddress((void**)&rowinv, g_rowinv);
    cudaGetSymbolAddress((void**)&rin,    g_rin);
    cudaGetSymbolAddress((void**)&rw,     g_rw);

    static int init_done = 0;
    if (!init_done) {
        cudaFuncSetAttribute(attn_fused_fp16,
                             cudaFuncAttributeMaxDynamicSharedMemorySize,
                             FS_HALVES * 2);
        cudaFuncSetAttribute(qkv_proj_fp16,
                             cudaFuncAttributeMaxDynamicSharedMemorySize,
                             GE_SMEM_BYTES);
        cudaFuncSetAttribute(o_proj_fp16,
                             cudaFuncAttributeMaxDynamicSharedMemorySize,
                             GE_SMEM_BYTES);
        init_done = 1;
    }

    const int NIN = BATCH * SEQ * DM;   // 4M
    const int NW  = DM * DM;            // 1M

    f2h_kernel<<<512, 256>>>(query, rin + 0 * (size_t)NIN, NIN / 8);
    f2h_kernel<<<512, 256>>>(key,   rin + 1 * (size_t)NIN, NIN / 8);
    f2h_kernel<<<512, 256>>>(value, rin + 2 * (size_t)NIN, NIN / 8);
    f2h_kernel<<<256, 256>>>(Wq, rw + 0 * (size_t)NW, NW / 8);
    f2h_kernel<<<256, 256>>>(Wk, rw + 1 * (size_t)NW, NW / 8);
    f2h_kernel<<<256, 256>>>(Wv, rw + 2 * (size_t)NW, NW / 8);
    f2h_kernel<<<256, 256>>>(Wo, rw + 3 * (size_t)NW, NW / 8);

    dim3 gqkv(DM / 128, MROWS / 128, 3);   // (8, 32, 3)
    qkv_proj_fp16<<<gqkv, 256, GE_SMEM_BYTES>>>(bq, bk, bv);

    dim3 gatt(SEQ / 128, BATCH * NH);      // (16, 32)
    attn_fused_fp16<<<gatt, 256, FS_HALVES * 2>>>(rowinv);

    dim3 gproj(DM / 128, MROWS / 128);     // (8, 32)
    o_proj_fp16<<<gproj, 256, GE_SMEM_BYTES>>>(bo, out);

    attn_write_fp16<<<gatt, 256>>>(attn, rowinv);
}

// round 15
// speedup vs baseline: 4.3221x; 1.0924x over previous
#include <cuda_runtime.h>
#include <cuda_fp16.h>
#include <mma.h>
#include <math.h>
#include <stdint.h>

using namespace nvcuda;

#define BATCH 2
#define SEQ   2048
#define DM    1024
#define NH    16
#define DEPTH 64
#define MROWS (BATCH * SEQ)       // 4096
#define NROWS (BATCH * NH * SEQ)  // 65536 attention rows

// Scratch (allocation-free rule: __device__ globals)
__device__ __half g_q[BATCH * SEQ * DM];
__device__ __half g_k[BATCH * SEQ * DM];
__device__ __half g_v[BATCH * SEQ * DM];
__device__ __half g_ctx[BATCH * SEQ * DM];
__device__ float  g_rowinv[NROWS];
__device__ __half g_rin[3][BATCH * SEQ * DM];   // fp16 inputs
__device__ __half g_rw[4][DM * DM];             // fp16 weights

__device__ __forceinline__ void cp_async16(void* smem, const void* gmem) {
    unsigned int s = (unsigned int)__cvta_generic_to_shared(smem);
    asm volatile("cp.async.cg.shared.global [%0], [%1], 16;\n" :: "r"(s), "l"(gmem));
}
__device__ __forceinline__ void cp_commit() {
    asm volatile("cp.async.commit_group;\n");
}
template <int N>
__device__ __forceinline__ void cp_wait() {
    asm volatile("cp.async.wait_group %0;\n" :: "n"(N));
}

// ---------------------------------------------------------------------------
// fp32 -> fp16 for all 7 tensors in ONE launch. blockIdx.z selects segment.
// ---------------------------------------------------------------------------
__global__ __launch_bounds__(256)
void f2h_all(const float* __restrict__ q, const float* __restrict__ k,
             const float* __restrict__ v,
             const float* __restrict__ wq, const float* __restrict__ wk,
             const float* __restrict__ wv, const float* __restrict__ wo)
{
    const int z = blockIdx.z;
    const float* src;
    __half* dst;
    int n8;
    if (z < 3) {
        src = (z == 0) ? q : (z == 1) ? k : v;
        dst = g_rin[z];
        n8  = (BATCH * SEQ * DM) / 8;
    } else {
        src = (z == 3) ? wq : (z == 4) ? wk : (z == 5) ? wv : wo;
        dst = g_rw[z - 3];
        n8  = (DM * DM) / 8;
    }
    const int stride = gridDim.x * 256;
    for (int i = blockIdx.x * 256 + threadIdx.x; i < n8; i += stride) {
        float4 a = ((const float4*)src)[2 * i];
        float4 b = ((const float4*)src)[2 * i + 1];
        __half2 h[4];
        h[0] = __floats2half2_rn(a.x, a.y);
        h[1] = __floats2half2_rn(a.z, a.w);
        h[2] = __floats2half2_rn(b.x, b.y);
        h[3] = __floats2half2_rn(b.z, b.w);
        ((uint2*)dst)[2 * i]     = *(uint2*)&h[0];
        ((uint2*)dst)[2 * i + 1] = *(uint2*)&h[2];
    }
}

// m16n16 f32 accumulator lane mapping (sm_80+ canonical):
//   lane = 4g+t; e0,e1,e4,e5 -> row g; e2,e3,e6,e7 -> row g+8
//   col = 2t + (e&1) + 8*(e>>2)
__device__ __forceinline__
void store_acc_half(__half* base, const float* x, int ldm, int lane,
                    float slo, float shi)
{
    const int g = lane >> 2, t = lane & 3;
    __half2 p;
    p = __floats2half2_rn(x[0] * slo, x[1] * slo);
    *(__half2*)(base + (size_t)g * ldm + 2 * t) = p;
    p = __floats2half2_rn(x[2] * shi, x[3] * shi);
    *(__half2*)(base + (size_t)(g + 8) * ldm + 2 * t) = p;
    p = __floats2half2_rn(x[4] * slo, x[5] * slo);
    *(__half2*)(base + (size_t)g * ldm + 2 * t + 8) = p;
    p = __floats2half2_rn(x[6] * shi, x[7] * shi);
    *(__half2*)(base + (size_t)(g + 8) * ldm + 2 * t + 8) = p;
}

// ---------------------------------------------------------------------------
// FP16 GEMM + bias, cp.async 2-stage, block 128x128, BK=32, 256 thr,
// 8 warps (4m x 2n), warp 32x64.
// ---------------------------------------------------------------------------
#define GA(s,r,c)  smh[(s) * 5120 + (r) * 40 + (c)]
#define GB(s,r,c)  smh[10240 + (s) * 4352 + (r) * 136 + (c)]
#define GE_SMEM_BYTES (18944 * 2 + 128 * 4)

template <bool OUT_HALF>
__device__ __forceinline__
void gemm_fp16_body(const __half* __restrict__ A, const __half* __restrict__ W,
                    const float* __restrict__ bias, void* __restrict__ C,
                    int K, int N, int bx, int by, float oscale)
{
    extern __shared__ __half smh[];
    float* sbias = (float*)(smh + 18944);

    const int tid  = threadIdx.x;
    const int lane = tid & 31;
    const int wid  = tid >> 5;
    const int brow = by * 128;
    const int bcol = bx * 128;
    const int wm   = (wid >> 1) * 32;
    const int wn   = (wid & 1) * 64;

    const int aRow = tid >> 2;            // 0..63
    const int aCol = (tid & 3) * 8;       // 0,8,16,24
    const int bRow = tid >> 4;            // 0..15
    const int bCol = (tid & 15) * 8;      // 0..120

    #pragma unroll
    for (int p = 0; p < 2; ++p)
        cp_async16(&GA(0, aRow + p * 64, aCol),
                   A + (size_t)(brow + aRow + p * 64) * K + aCol);
    #pragma unroll
    for (int p = 0; p < 2; ++p)
        cp_async16(&GB(0, bRow + p * 16, bCol),
                   W + (size_t)(bRow + p * 16) * N + bcol + bCol);
    cp_commit();

    if (tid < 128) sbias[tid] = bias[bcol + tid];

    wmma::fragment<wmma::accumulator, 16, 16, 16, float> acc[2][4];
    #pragma unroll
    for (int i = 0; i < 2; ++i)
        #pragma unroll
        for (int j = 0; j < 4; ++j)
            wmma::fill_fragment(acc[i][j], 0.0f);

    const int NCH = K / 32;
    for (int c = 0; c < NCH; ++c) {
        if (c + 1 < NCH) {
            const int s = (c + 1) & 1;
            const int k0 = (c + 1) * 32;
            #pragma unroll
            for (int p = 0; p < 2; ++p)
                cp_async16(&GA(s, aRow + p * 64, aCol),
                           A + (size_t)(brow + aRow + p * 64) * K + k0 + aCol);
            #pragma unroll
            for (int p = 0; p < 2; ++p)
                cp_async16(&GB(s, bRow + p * 16, bCol),
                           W + (size_t)(k0 + bRow + p * 16) * N + bcol + bCol);
            cp_commit();
            cp_wait<1>();
        } else {
            cp_wait<0>();
        }
        __syncthreads();

        const int s = c & 1;
        #pragma unroll
        for (int kk = 0; kk < 32; kk += 16) {
            wmma::fragment<wmma::matrix_a, 16, 16, 16, __half,
                           wmma::row_major> af[2];
            wmma::fragment<wmma::matrix_b, 16, 16, 16, __half,
                           wmma::row_major> bf[4];
            #pragma unroll
            for (int i = 0; i < 2; ++i)
                wmma::load_matrix_sync(af[i], &GA(s, wm + i * 16, kk), 40);
            #pragma unroll
            for (int j = 0; j < 4; ++j)
                wmma::load_matrix_sync(bf[j], &GB(s, kk, wn + j * 16), 136);
            #pragma unroll
            for (int i = 0; i < 2; ++i)
                #pragma unroll
                for (int j = 0; j < 4; ++j)
                    wmma::mma_sync(acc[i][j], af[i], bf[j], acc[i][j]);
        }
        __syncthreads();
    }

    const int t = lane & 3;
    #pragma unroll
    for (int i = 0; i < 2; ++i)
        #pragma unroll
        for (int j = 0; j < 4; ++j) {
            const int cb = wn + j * 16 + 2 * t;
            const float b0 = sbias[cb],     b1 = sbias[cb + 1];
            const float b4 = sbias[cb + 8], b5 = sbias[cb + 9];
            acc[i][j].x[0] += b0; acc[i][j].x[1] += b1;
            acc[i][j].x[2] += b0; acc[i][j].x[3] += b1;
            acc[i][j].x[4] += b4; acc[i][j].x[5] += b5;
            acc[i][j].x[6] += b4; acc[i][j].x[7] += b5;
            if (OUT_HALF) {
                __half* out = (__half*)C;
                store_acc_half(out + (size_t)(brow + wm + i * 16) * N
                                   + bcol + wn + j * 16,
                               acc[i][j].x, N, lane, oscale, oscale);
            } else {
                wmma::store_matrix_sync(
                    (float*)C + (size_t)(brow + wm + i * 16) * N
                              + bcol + wn + j * 16,
                    acc[i][j], N, wmma::mem_row_major);
            }
        }
}

__global__ __launch_bounds__(256)
void qkv_proj_fp16(const float* __restrict__ bq, const float* __restrict__ bk,
                   const float* __restrict__ bv)
{
    const int z = blockIdx.z;
    const __half* A    = g_rin[z];
    const __half* W    = g_rw[z];
    const float* bias  = (z == 0) ? bq : (z == 1) ? bk : bv;
    __half*      C     = (z == 0) ? g_q : (z == 1) ? g_k : g_v;
    const float  scale = (z == 0) ? 0.125f : 1.0f;
    gemm_fp16_body<true>(A, W, bias, C, DM, DM, blockIdx.x, blockIdx.y, scale);
}

__global__ __launch_bounds__(256)
void o_proj_fp16(const float* __restrict__ bias, float* __restrict__ out)
{
    gemm_fp16_body<false>(g_ctx, g_rw[3], bias, out, DM, DM,
                          blockIdx.x, blockIdx.y, 1.0f);
}

// ---------------------------------------------------------------------------
// Fused attention pass A: NO attn gmem writes. Per block = (bh, 128 q-rows).
// smem halves: Qs[128][72] | KE[128][136] | Vs[128][72] = 71680 B
// ---------------------------------------------------------------------------
#define FQ_OFF  0
#define FK_OFF  9216
#define FV_OFF  (9216 + 17408)
#define FS_HALVES (9216 + 17408 + 9216)

__global__ __launch_bounds__(256)
void attn_fused_fp16(float* __restrict__ rowinv_g)
{
    extern __shared__ __half smh[];
    __half* Qs = smh + FQ_OFF;   // [128][72]
    __half* KE = smh + FK_OFF;   // K: [128] stride 72 ; E: [128] stride 136
    __half* Vs = smh + FV_OFF;   // [128][72]
    __shared__ float psum[128];

    const int bh = blockIdx.y;
    const int b  = bh >> 4;
    const int h  = bh & 15;
    const int i0 = blockIdx.x * 128;
    const int tid  = threadIdx.x;
    const int lane = tid & 31;
    const int wid  = tid >> 5;
    const int wm   = (wid >> 1) * 32;
    const int wn   = (wid & 1) * 64;
    const int cn   = (wid & 1) * 32;

    const __half* qbase = g_q + (size_t)b * SEQ * DM + h * DEPTH;
    const __half* kbase = g_k + (size_t)b * SEQ * DM + h * DEPTH;
    const __half* vbase = g_v + (size_t)b * SEQ * DM + h * DEPTH;

    if (tid < 128) psum[tid] = 0.0f;

    const int lR = tid >> 3;          // 0..31
    const int lC = (tid & 7) * 8;     // 0..56
    #pragma unroll
    for (int p = 0; p < 4; ++p) {
        const int r = lR + p * 32;
        *(uint4*)&Qs[r * 72 + lC] =
            *(const uint4*)(qbase + (size_t)(i0 + r) * DM + lC);
    }

    wmma::fragment<wmma::accumulator, 16, 16, 16, float> cacc[2][2];
    #pragma unroll
    for (int i = 0; i < 2; ++i)
        #pragma unroll
        for (int j = 0; j < 2; ++j)
            wmma::fill_fragment(cacc[i][j], 0.0f);

    float lo[2] = {0.0f, 0.0f};
    float hi[2] = {0.0f, 0.0f};

    for (int jt = 0; jt < 16; ++jt) {
        const int j0 = jt * 128;

        __syncthreads();   // prev EV done: KE/Vs free
        #pragma unroll
        for (int p = 0; p < 4; ++p) {
            const int r = lR + p * 32;
            *(uint4*)&KE[r * 72 + lC] =
                *(const uint4*)(kbase + (size_t)(j0 + r) * DM + lC);
            *(uint4*)&Vs[r * 72 + lC] =
                *(const uint4*)(vbase + (size_t)(j0 + r) * DM + lC);
        }
        __syncthreads();

        wmma::fragment<wmma::accumulator, 16, 16, 16, float> sacc[2][4];
        #pragma unroll
        for (int i = 0; i < 2; ++i)
            #pragma unroll
            for (int j = 0; j < 4; ++j)
                wmma::fill_fragment(sacc[i][j], 0.0f);

        #pragma unroll
        for (int kk = 0; kk < DEPTH; kk += 16) {
            wmma::fragment<wmma::matrix_a, 16, 16, 16, __half,
                           wmma::row_major> af[2];
            wmma::fragment<wmma::matrix_b, 16, 16, 16, __half,
                           wmma::col_major> bf[4];
            #pragma unroll
            for (int i = 0; i < 2; ++i)
                wmma::load_matrix_sync(af[i], &Qs[(wm + i * 16) * 72 + kk], 72);
            #pragma unroll
            for (int j = 0; j < 4; ++j)
                wmma::load_matrix_sync(bf[j], &KE[(wn + j * 16) * 72 + kk], 72);
            #pragma unroll
            for (int i = 0; i < 2; ++i)
                #pragma unroll
                for (int j = 0; j < 4; ++j)
                    wmma::mma_sync(sacc[i][j], af[i], bf[j], sacc[i][j]);
        }

        #pragma unroll
        for (int i = 0; i < 2; ++i)
            #pragma unroll
            for (int j = 0; j < 4; ++j)
                #pragma unroll
                for (int e = 0; e < 8; ++e) {
                    const float x = __expf(sacc[i][j].x[e]);
                    sacc[i][j].x[e] = x;
                    if ((e & 3) < 2) lo[i] += x; else hi[i] += x;
                }

        __syncthreads();   // all warps done reading K from KE

        #pragma unroll
        for (int i = 0; i < 2; ++i)
            #pragma unroll
            for (int j = 0; j < 4; ++j)
                store_acc_half(&KE[(wm + i * 16) * 136 + wn + j * 16],
                               sacc[i][j].x, 136, lane, 1.0f, 1.0f);
        __syncthreads();   // E visible

        #pragma unroll
        for (int kk = 0; kk < 128; kk += 16) {
            wmma::fragment<wmma::matrix_a, 16, 16, 16, __half,
                           wmma::row_major> af[2];
            wmma::fragment<wmma::matrix_b, 16, 16, 16, __half,
                           wmma::row_major> bf[2];
            #pragma unroll
            for (int i = 0; i < 2; ++i)
                wmma::load_matrix_sync(af[i], &KE[(wm + i * 16) * 136 + kk], 136);
            #pragma unroll
            for (int j = 0; j < 2; ++j)
                wmma::load_matrix_sync(bf[j], &Vs[kk * 72 + cn + j * 16], 72);
            #pragma unroll
            for (int i = 0; i < 2; ++i)
                #pragma unroll
                for (int j = 0; j < 2; ++j)
                    wmma::mma_sync(cacc[i][j], af[i], bf[j], cacc[i][j]);
        }
    }

    #pragma unroll
    for (int i = 0; i < 2; ++i) {
        lo[i] += __shfl_xor_sync(0xffffffffu, lo[i], 1);
        lo[i] += __shfl_xor_sync(0xffffffffu, lo[i], 2);
        hi[i] += __shfl_xor_sync(0xffffffffu, hi[i], 1);
        hi[i] += __shfl_xor_sync(0xffffffffu, hi[i], 2);
    }
    __syncthreads();
    if ((lane & 3) == 0) {
        const int g = lane >> 2;
        #pragma unroll
        for (int i = 0; i < 2; ++i) {
            atomicAdd(&psum[wm + i * 16 + g],     lo[i]);
            atomicAdd(&psum[wm + i * 16 + 8 + g], hi[i]);
        }
    }
    __syncthreads();
    if (tid < 128) {
        const float inv = 1.0f / psum[tid];
        psum[tid] = inv;
        rowinv_g[(size_t)bh * SEQ + i0 + tid] = inv;
    }
    __syncthreads();

    const int g = lane >> 2;
    #pragma unroll
    for (int i = 0; i < 2; ++i) {
        const float ivlo = psum[wm + i * 16 + g];
        const float ivhi = psum[wm + i * 16 + 8 + g];
        #pragma unroll
        for (int j = 0; j < 2; ++j)
            store_acc_half(g_ctx + (size_t)(b * SEQ + i0 + wm + i * 16) * DM
                               + h * DEPTH + cn + j * 16,
                           cacc[i][j].x, DM, lane, ivlo, ivhi);
    }
}

// ---------------------------------------------------------------------------
// Pass B: scores replay, cp.async double-buffered K.
// attn = __expf(S) * rowinv written ONCE, fp32 streaming stores.
// Dynamic smem: Qs[128*72] | Ks[2][128*72] halves | invs[128] floats = 55808 B
// ---------------------------------------------------------------------------
#define AW_Q   0
#define AW_K(s) (9216 + (s) * 9216)
#define AW_SMEM_BYTES (27648 * 2 + 128 * 4)

__global__ __launch_bounds__(256)
void attn_write_fp16(float* __restrict__ attn, const float* __restrict__ rowinv)
{
    extern __shared__ __half smh[];
    __half* Qs = smh + AW_Q;
    float* invs = (float*)(smh + 27648);

    const int bh = blockIdx.y;
    const int b  = bh >> 4;
    const int h  = bh & 15;
    const int i0 = blockIdx.x * 128;
    const int tid  = threadIdx.x;
    const int lane = tid & 31;
    const int wid  = tid >> 5;
    const int wm   = (wid >> 1) * 32;
    const int wn   = (wid & 1) * 64;

    const __half* qbase = g_q + (size_t)b * SEQ * DM + h * DEPTH;
    const __half* kbase = g_k + (size_t)b * SEQ * DM + h * DEPTH;
    float* obase = attn + (size_t)bh * SEQ * SEQ;

    const int lR = tid >> 3;          // 0..31
    const int lC = (tid & 7) * 8;     // 0..56

    // Prefetch K tile 0 into stage 0
    #pragma unroll
    for (int p = 0; p < 4; ++p) {
        const int r = lR + p * 32;
        cp_async16(&smh[AW_K(0) + r * 72 + lC],
                   kbase + (size_t)r * DM + lC);
    }
    cp_commit();

    // Q tile + rowinv (regular loads, overlap with cp.async)
    #pragma unroll
    for (int p = 0; p < 4; ++p) {
        const int r = lR + p * 32;
        *(uint4*)&Qs[r * 72 + lC] =
            *(const uint4*)(qbase + (size_t)(i0 + r) * DM + lC);
    }
    if (tid < 128) invs[tid] = rowinv[(size_t)bh * SEQ + i0 + tid];

    const int g = lane >> 2, t = lane & 3;

    for (int jt = 0; jt < 16; ++jt) {
        const int j0 = jt * 128;

        __syncthreads();   // all warps done reading buf[(jt+1)&1] (iter jt-1)
        if (jt + 1 < 16) {
            const int s = (jt + 1) & 1;
            const int jn = (jt + 1) * 128;
            #pragma unroll
            for (int p = 0; p < 4; ++p) {
                const int r = lR + p * 32;
                cp_async16(&smh[AW_K(s) + r * 72 + lC],
                           kbase + (size_t)(jn + r) * DM + lC);
            }
            cp_commit();
            cp_wait<1>();
        } else {
            cp_wait<0>();
        }
        __syncthreads();   // K(jt) visible

        const __half* Ks = smh + AW_K(jt & 1);

        wmma::fragment<wmma::accumulator, 16, 16, 16, float> sacc[2][4];
        #pragma unroll
        for (int i = 0; i < 2; ++i)
            #pragma unroll
            for (int j = 0; j < 4; ++j)
                wmma::fill_fragment(sacc[i][j], 0.0f);

        #pragma unroll
        for (int kk = 0; kk < DEPTH; kk += 16) {
            wmma::fragment<wmma::matrix_a, 16, 16, 16, __half,
                           wmma::row_major> af[2];
            wmma::fragment<wmma::matrix_b, 16, 16, 16, __half,
                           wmma::col_major> bf[4];
            #pragma unroll
            for (int i = 0; i < 2; ++i)
                wmma::load_matrix_sync(af[i], &Qs[(wm + i * 16) * 72 + kk], 72);
            #pragma unroll
            for (int j = 0; j < 4; ++j)
                wmma::load_matrix_sync(bf[j], &Ks[(wn + j * 16) * 72 + kk], 72);
            #pragma unroll
            for (int i = 0; i < 2; ++i)
                #pragma unroll
                for (int j = 0; j < 4; ++j)
                    wmma::mma_sync(sacc[i][j], af[i], bf[j], sacc[i][j]);
        }

        #pragma unroll
        for (int i = 0; i < 2; ++i) {
            const float ivlo = invs[wm + i * 16 + g];
            const float ivhi = invs[wm + i * 16 + 8 + g];
            #pragma unroll
            for (int j = 0; j < 4; ++j) {
                float* base = obase + (size_t)(i0 + wm + i * 16) * SEQ
                            + j0 + wn + j * 16;
                const float* x = sacc[i][j].x;
                float2 v;
                v.x = __expf(x[0]) * ivlo; v.y = __expf(x[1]) * ivlo;
                __stcs((float2*)(base + (size_t)g * SEQ + 2 * t), v);
                v.x = __expf(x[2]) * ivhi; v.y = __expf(x[3]) * ivhi;
                __stcs((float2*)(base + (size_t)(g + 8) * SEQ + 2 * t), v);
                v.x = __expf(x[4]) * ivlo; v.y = __expf(x[5]) * ivlo;
                __stcs((float2*)(base + (size_t)g * SEQ + 2 * t + 8), v);
                v.x = __expf(x[6]) * ivhi; v.y = __expf(x[7]) * ivhi;
                __stcs((float2*)(base + (size_t)(g + 8) * SEQ + 2 * t + 8), v);
            }
        }
    }
}

// ---------------------------------------------------------------------------
extern "C" void kernel_launch(void* const* d_in, const int* in_sizes, int n_in,
                              void* d_out, int out_size)
{
    const float* query = (const float*)d_in[0];
    const float* key   = (const float*)d_in[1];
    const float* value = (const float*)d_in[2];
    const float* bq = (const float*)d_in[4];
    const float* Wq = (const float*)d_in[3];
    const float* Wk = (const float*)d_in[5];
    const float* bk = (const float*)d_in[6];
    const float* Wv = (const float*)d_in[7];
    const float* bv = (const float*)d_in[8];
    const float* Wo = (const float*)d_in[9];
    const float* bo = (const float*)d_in[10];

    float* out  = (float*)d_out;
    float* attn = out + (size_t)BATCH * SEQ * DM;

    float* rowinv;
    cudaGetSymbolAddress((void**)&rowinv, g_rowinv);

    static int init_done = 0;
    static cudaStream_t s2;
    static cudaEvent_t ev1, ev2;
    if (!init_done) {
        cudaFuncSetAttribute(attn_fused_fp16,
                             cudaFuncAttributeMaxDynamicSharedMemorySize,
                             FS_HALVES * 2);
        cudaFuncSetAttribute(qkv_proj_fp16,
                             cudaFuncAttributeMaxDynamicSharedMemorySize,
                             GE_SMEM_BYTES);
        cudaFuncSetAttribute(o_proj_fp16,
                             cudaFuncAttributeMaxDynamicSharedMemorySize,
                             GE_SMEM_BYTES);
        cudaFuncSetAttribute(attn_write_fp16,
                             cudaFuncAttributeMaxDynamicSharedMemorySize,
                             AW_SMEM_BYTES);
        cudaStreamCreateWithFlags(&s2, cudaStreamNonBlocking);
        cudaEventCreateWithFlags(&ev1, cudaEventDisableTiming);
        cudaEventCreateWithFlags(&ev2, cudaEventDisableTiming);
        init_done = 1;
    }

    // One launch converts all 7 tensors to fp16
    dim3 gcvt(256, 1, 7);
    f2h_all<<<gcvt, 256>>>(query, key, value, Wq, Wk, Wv, Wo);

    dim3 gqkv(DM / 128, MROWS / 128, 3);   // (8, 32, 3)
    qkv_proj_fp16<<<gqkv, 256, GE_SMEM_BYTES>>>(bq, bk, bv);

    dim3 gatt(SEQ / 128, BATCH * NH);      // (16, 32)
    attn_fused_fp16<<<gatt, 256, FS_HALVES * 2>>>(rowinv);

    // Fork: attn_write (side stream) runs concurrently with o_proj (main)
    cudaEventRecord(ev1, 0);
    cudaStreamWaitEvent(s2, ev1, 0);
    attn_write_fp16<<<gatt, 256, AW_SMEM_BYTES, s2>>>(attn, rowinv);

    dim3 gproj(DM / 128, MROWS / 128);     // (8, 32)
    o_proj_fp16<<<gproj, 256, GE_SMEM_BYTES>>>(bo, out);

    // Join
    cudaEventRecord(ev2, s2);
    cudaStreamWaitEvent(0, ev2, 0);
}

// round 17
// speedup vs baseline: 4.4276x; 1.0244x over previous
#include <cuda_runtime.h>
#include <cuda_fp16.h>
#include <mma.h>
#include <math.h>
#include <stdint.h>

using namespace nvcuda;

#define BATCH 2
#define SEQ   2048
#define DM    1024
#define NH    16
#define DEPTH 64
#define MROWS (BATCH * SEQ)       // 4096
#define NROWS (BATCH * NH * SEQ)  // 65536 attention rows

// Scratch (allocation-free rule: __device__ globals)
__device__ __half g_q[BATCH * SEQ * DM];
__device__ __half g_k[BATCH * SEQ * DM];
__device__ __half g_v[BATCH * SEQ * DM];
__device__ __half g_ctx[BATCH * SEQ * DM];
__device__ float  g_rowinv[NROWS];
__device__ __half g_rin[3][BATCH * SEQ * DM];   // fp16 inputs
__device__ __half g_rw[4][DM * DM];             // fp16 weights

__device__ __forceinline__ void cp_async16(void* smem, const void* gmem) {
    unsigned int s = (unsigned int)__cvta_generic_to_shared(smem);
    asm volatile("cp.async.cg.shared.global [%0], [%1], 16;\n" :: "r"(s), "l"(gmem));
}
__device__ __forceinline__ void cp_commit() {
    asm volatile("cp.async.commit_group;\n");
}
template <int N>
__device__ __forceinline__ void cp_wait() {
    asm volatile("cp.async.wait_group %0;\n" :: "n"(N));
}

// ---------------------------------------------------------------------------
// fp32 -> fp16 for all 7 tensors in ONE launch. blockIdx.z selects segment.
// ---------------------------------------------------------------------------
__global__ __launch_bounds__(256)
void f2h_all(const float* __restrict__ q, const float* __restrict__ k,
             const float* __restrict__ v,
             const float* __restrict__ wq, const float* __restrict__ wk,
             const float* __restrict__ wv, const float* __restrict__ wo)
{
    const int z = blockIdx.z;
    const float* src;
    __half* dst;
    int n8;
    if (z < 3) {
        src = (z == 0) ? q : (z == 1) ? k : v;
        dst = g_rin[z];
        n8  = (BATCH * SEQ * DM) / 8;
    } else {
        src = (z == 3) ? wq : (z == 4) ? wk : (z == 5) ? wv : wo;
        dst = g_rw[z - 3];
        n8  = (DM * DM) / 8;
    }
    const int stride = gridDim.x * 256;
    for (int i = blockIdx.x * 256 + threadIdx.x; i < n8; i += stride) {
        float4 a = ((const float4*)src)[2 * i];
        float4 b = ((const float4*)src)[2 * i + 1];
        __half2 h[4];
        h[0] = __floats2half2_rn(a.x, a.y);
        h[1] = __floats2half2_rn(a.z, a.w);
        h[2] = __floats2half2_rn(b.x, b.y);
        h[3] = __floats2half2_rn(b.z, b.w);
        ((uint2*)dst)[2 * i]     = *(uint2*)&h[0];
        ((uint2*)dst)[2 * i + 1] = *(uint2*)&h[2];
    }
}

// m16n16 f32 accumulator lane mapping (sm_80+ canonical):
//   lane = 4g+t; e0,e1,e4,e5 -> row g; e2,e3,e6,e7 -> row g+8
//   col = 2t + (e&1) + 8*(e>>2)
__device__ __forceinline__
void store_acc_half(__half* base, const float* x, int ldm, int lane,
                    float slo, float shi)
{
    const int g = lane >> 2, t = lane & 3;
    __half2 p;
    p = __floats2half2_rn(x[0] * slo, x[1] * slo);
    *(__half2*)(base + (size_t)g * ldm + 2 * t) = p;
    p = __floats2half2_rn(x[2] * shi, x[3] * shi);
    *(__half2*)(base + (size_t)(g + 8) * ldm + 2 * t) = p;
    p = __floats2half2_rn(x[4] * slo, x[5] * slo);
    *(__half2*)(base + (size_t)g * ldm + 2 * t + 8) = p;
    p = __floats2half2_rn(x[6] * shi, x[7] * shi);
    *(__half2*)(base + (size_t)(g + 8) * ldm + 2 * t + 8) = p;
}

// ---------------------------------------------------------------------------
// FP16 GEMM + bias, cp.async 2-stage, block 128x128, BK=32, 256 thr,
// 8 warps (4m x 2n), warp 32x64.
// ---------------------------------------------------------------------------
#define GA(s,r,c)  smh[(s) * 5120 + (r) * 40 + (c)]
#define GB(s,r,c)  smh[10240 + (s) * 4352 + (r) * 136 + (c)]
#define GE_SMEM_BYTES (18944 * 2 + 128 * 4)

template <bool OUT_HALF>
__device__ __forceinline__
void gemm_fp16_body(const __half* __restrict__ A, const __half* __restrict__ W,
                    const float* __restrict__ bias, void* __restrict__ C,
                    int K, int N, int bx, int by, float oscale)
{
    extern __shared__ __half smh[];
    float* sbias = (float*)(smh + 18944);

    const int tid  = threadIdx.x;
    const int lane = tid & 31;
    const int wid  = tid >> 5;
    const int brow = by * 128;
    const int bcol = bx * 128;
    const int wm   = (wid >> 1) * 32;
    const int wn   = (wid & 1) * 64;

    const int aRow = tid >> 2;            // 0..63
    const int aCol = (tid & 3) * 8;       // 0,8,16,24
    const int bRow = tid >> 4;            // 0..15
    const int bCol = (tid & 15) * 8;      // 0..120

    #pragma unroll
    for (int p = 0; p < 2; ++p)
        cp_async16(&GA(0, aRow + p * 64, aCol),
                   A + (size_t)(brow + aRow + p * 64) * K + aCol);
    #pragma unroll
    for (int p = 0; p < 2; ++p)
        cp_async16(&GB(0, bRow + p * 16, bCol),
                   W + (size_t)(bRow + p * 16) * N + bcol + bCol);
    cp_commit();

    if (tid < 128) sbias[tid] = bias[bcol + tid];

    wmma::fragment<wmma::accumulator, 16, 16, 16, float> acc[2][4];
    #pragma unroll
    for (int i = 0; i < 2; ++i)
        #pragma unroll
        for (int j = 0; j < 4; ++j)
            wmma::fill_fragment(acc[i][j], 0.0f);

    const int NCH = K / 32;
    for (int c = 0; c < NCH; ++c) {
        if (c + 1 < NCH) {
            const int s = (c + 1) & 1;
            const int k0 = (c + 1) * 32;
            #pragma unroll
            for (int p = 0; p < 2; ++p)
                cp_async16(&GA(s, aRow + p * 64, aCol),
                           A + (size_t)(brow + aRow + p * 64) * K + k0 + aCol);
            #pragma unroll
            for (int p = 0; p < 2; ++p)
                cp_async16(&GB(s, bRow + p * 16, bCol),
                           W + (size_t)(k0 + bRow + p * 16) * N + bcol + bCol);
            cp_commit();
            cp_wait<1>();
        } else {
            cp_wait<0>();
        }
        __syncthreads();

        const int s = c & 1;
        #pragma unroll
        for (int kk = 0; kk < 32; kk += 16) {
            wmma::fragment<wmma::matrix_a, 16, 16, 16, __half,
                           wmma::row_major> af[2];
            wmma::fragment<wmma::matrix_b, 16, 16, 16, __half,
                           wmma::row_major> bf[4];
            #pragma unroll
            for (int i = 0; i < 2; ++i)
                wmma::load_matrix_sync(af[i], &GA(s, wm + i * 16, kk), 40);
            #pragma unroll
            for (int j = 0; j < 4; ++j)
                wmma::load_matrix_sync(bf[j], &GB(s, kk, wn + j * 16), 136);
            #pragma unroll
            for (int i = 0; i < 2; ++i)
                #pragma unroll
                for (int j = 0; j < 4; ++j)
                    wmma::mma_sync(acc[i][j], af[i], bf[j], acc[i][j]);
        }
        __syncthreads();
    }

    const int t = lane & 3;
    #pragma unroll
    for (int i = 0; i < 2; ++i)
        #pragma unroll
        for (int j = 0; j < 4; ++j) {
            const int cb = wn + j * 16 + 2 * t;
            const float b0 = sbias[cb],     b1 = sbias[cb + 1];
            const float b4 = sbias[cb + 8], b5 = sbias[cb + 9];
            acc[i][j].x[0] += b0; acc[i][j].x[1] += b1;
            acc[i][j].x[2] += b0; acc[i][j].x[3] += b1;
            acc[i][j].x[4] += b4; acc[i][j].x[5] += b5;
            acc[i][j].x[6] += b4; acc[i][j].x[7] += b5;
            if (OUT_HALF) {
                __half* out = (__half*)C;
                store_acc_half(out + (size_t)(brow + wm + i * 16) * N
                                   + bcol + wn + j * 16,
                               acc[i][j].x, N, lane, oscale, oscale);
            } else {
                wmma::store_matrix_sync(
                    (float*)C + (size_t)(brow + wm + i * 16) * N
                              + bcol + wn + j * 16,
                    acc[i][j], N, wmma::mem_row_major);
            }
        }
}

__global__ __launch_bounds__(256)
void qkv_proj_fp16(const float* __restrict__ bq, const float* __restrict__ bk,
                   const float* __restrict__ bv)
{
    const int z = blockIdx.z;
    const __half* A    = g_rin[z];
    const __half* W    = g_rw[z];
    const float* bias  = (z == 0) ? bq : (z == 1) ? bk : bv;
    __half*      C     = (z == 0) ? g_q : (z == 1) ? g_k : g_v;
    const float  scale = (z == 0) ? 0.125f : 1.0f;
    gemm_fp16_body<true>(A, W, bias, C, DM, DM, blockIdx.x, blockIdx.y, scale);
}

__global__ __launch_bounds__(256)
void o_proj_fp16(const float* __restrict__ bias, float* __restrict__ out)
{
    gemm_fp16_body<false>(g_ctx, g_rw[3], bias, out, DM, DM,
                          blockIdx.x, blockIdx.y, 1.0f);
}

// ---------------------------------------------------------------------------
// Fused attention pass A: cp.async double-buffered K/V, dedicated E buffer.
// Per block = (bh, 128 q-rows); 16 key tiles:
//   S = Qs K^T -> exp (fp32, rowsums) -> half E -> ctx += E V.
// smem halves: Qs[128][72] | K[2][128][72] | V[2][128][72] | E[128][136]
//            = 9216 + 18432 + 18432 + 17408 = 63488 halves = 126976 B
// ---------------------------------------------------------------------------
#define FQ      0
#define FK(s)   (9216 + (s) * 9216)
#define FV(s)   (27648 + (s) * 9216)
#define FE      46080
#define FS_HALVES 63488

__global__ __launch_bounds__(256)
void attn_fused_fp16(float* __restrict__ rowinv_g)
{
    extern __shared__ __half smh[];
    __half* Qs = smh + FQ;
    __half* Es = smh + FE;
    __shared__ float psum[128];

    const int bh = blockIdx.y;
    const int b  = bh >> 4;
    const int h  = bh & 15;
    const int i0 = blockIdx.x * 128;
    const int tid  = threadIdx.x;
    const int lane = tid & 31;
    const int wid  = tid >> 5;
    const int wm   = (wid >> 1) * 32;
    const int wn   = (wid & 1) * 64;
    const int cn   = (wid & 1) * 32;

    const __half* qbase = g_q + (size_t)b * SEQ * DM + h * DEPTH;
    const __half* kbase = g_k + (size_t)b * SEQ * DM + h * DEPTH;
    const __half* vbase = g_v + (size_t)b * SEQ * DM + h * DEPTH;

    if (tid < 128) psum[tid] = 0.0f;

    const int lR = tid >> 3;          // 0..31
    const int lC = (tid & 7) * 8;     // 0..56

    // Prefetch K/V tile 0 into stage 0
    #pragma unroll
    for (int p = 0; p < 4; ++p) {
        const int r = lR + p * 32;
        cp_async16(&smh[FK(0) + r * 72 + lC], kbase + (size_t)r * DM + lC);
        cp_async16(&smh[FV(0) + r * 72 + lC], vbase + (size_t)r * DM + lC);
    }
    cp_commit();

    // Q tile (regular loads, overlaps with cp.async)
    #pragma unroll
    for (int p = 0; p < 4; ++p) {
        const int r = lR + p * 32;
        *(uint4*)&Qs[r * 72 + lC] =
            *(const uint4*)(qbase + (size_t)(i0 + r) * DM + lC);
    }

    wmma::fragment<wmma::accumulator, 16, 16, 16, float> cacc[2][2];
    #pragma unroll
    for (int i = 0; i < 2; ++i)
        #pragma unroll
        for (int j = 0; j < 2; ++j)
            wmma::fill_fragment(cacc[i][j], 0.0f);

    float lo[2] = {0.0f, 0.0f};
    float hi[2] = {0.0f, 0.0f};

    for (int jt = 0; jt < 16; ++jt) {
        __syncthreads();   // all warps fully done with iter jt-1 (K/V/E reads)
        if (jt + 1 < 16) {
            const int s = (jt + 1) & 1;
            const int jn = (jt + 1) * 128;
            #pragma unroll
            for (int p = 0; p < 4; ++p) {
                const int r = lR + p * 32;
                cp_async16(&smh[FK(s) + r * 72 + lC],
                           kbase + (size_t)(jn + r) * DM + lC);
                cp_async16(&smh[FV(s) + r * 72 + lC],
                           vbase + (size_t)(jn + r) * DM + lC);
            }
            cp_commit();
            cp_wait<1>();
        } else {
            cp_wait<0>();
        }
        __syncthreads();   // K/V(jt) visible (and Q on first iter)

        const __half* Ks = smh + FK(jt & 1);
        const __half* Vs = smh + FV(jt & 1);

        // S = Q K^T  (warp 32x64, depth 64 = 4 k16-steps)
        wmma::fragment<wmma::accumulator, 16, 16, 16, float> sacc[2][4];
        #pragma unroll
        for (int i = 0; i < 2; ++i)
            #pragma unroll
            for (int j = 0; j < 4; ++j)
                wmma::fill_fragment(sacc[i][j], 0.0f);

        #pragma unroll
        for (int kk = 0; kk < DEPTH; kk += 16) {
            wmma::fragment<wmma::matrix_a, 16, 16, 16, __half,
                           wmma::row_major> af[2];
            wmma::fragment<wmma::matrix_b, 16, 16, 16, __half,
                           wmma::col_major> bf[4];
            #pragma unroll
            for (int i = 0; i < 2; ++i)
                wmma::load_matrix_sync(af[i], &Qs[(wm + i * 16) * 72 + kk], 72);
            #pragma unroll
            for (int j = 0; j < 4; ++j)
                wmma::load_matrix_sync(bf[j], &Ks[(wn + j * 16) * 72 + kk], 72);
            #pragma unroll
            for (int i = 0; i < 2; ++i)
                #pragma unroll
                for (int j = 0; j < 4; ++j)
                    wmma::mma_sync(sacc[i][j], af[i], bf[j], sacc[i][j]);
        }

        // exp (fp32) + rowsums; E -> dedicated smem buffer (half)
        #pragma unroll
        for (int i = 0; i < 2; ++i)
            #pragma unroll
            for (int j = 0; j < 4; ++j) {
                #pragma unroll
                for (int e = 0; e < 8; ++e) {
                    const float x = __expf(sacc[i][j].x[e]);
                    sacc[i][j].x[e] = x;
                    if ((e & 3) < 2) lo[i] += x; else hi[i] += x;
                }
                store_acc_half(&Es[(wm + i * 16) * 136 + wn + j * 16],
                               sacc[i][j].x, 136, lane, 1.0f, 1.0f);
            }
        __syncthreads();   // E visible

        // ctx += E V  (warp 32x32, K=128 = 8 k16-steps)
        #pragma unroll
        for (int kk = 0; kk < 128; kk += 16) {
            wmma::fragment<wmma::matrix_a, 16, 16, 16, __half,
                           wmma::row_major> af[2];
            wmma::fragment<wmma::matrix_b, 16, 16, 16, __half,
                           wmma::row_major> bf[2];
            #pragma unroll
            for (int i = 0; i < 2; ++i)
                wmma::load_matrix_sync(af[i], &Es[(wm + i * 16) * 136 + kk], 136);
            #pragma unroll
            for (int j = 0; j < 2; ++j)
                wmma::load_matrix_sync(bf[j], &Vs[kk * 72 + cn + j * 16], 72);
            #pragma unroll
            for (int i = 0; i < 2; ++i)
                #pragma unroll
                for (int j = 0; j < 2; ++j)
                    wmma::mma_sync(cacc[i][j], af[i], bf[j], cacc[i][j]);
        }
    }

    // Deterministic rowsum -> rowinv
    #pragma unroll
    for (int i = 0; i < 2; ++i) {
        lo[i] += __shfl_xor_sync(0xffffffffu, lo[i], 1);
        lo[i] += __shfl_xor_sync(0xffffffffu, lo[i], 2);
        hi[i] += __shfl_xor_sync(0xffffffffu, hi[i], 1);
        hi[i] += __shfl_xor_sync(0xffffffffu, hi[i], 2);
    }
    __syncthreads();
    if ((lane & 3) == 0) {
        const int g = lane >> 2;
        #pragma unroll
        for (int i = 0; i < 2; ++i) {
            atomicAdd(&psum[wm + i * 16 + g],     lo[i]);
            atomicAdd(&psum[wm + i * 16 + 8 + g], hi[i]);
        }
    }
    __syncthreads();
    if (tid < 128) {
        const float inv = 1.0f / psum[tid];
        psum[tid] = inv;
        rowinv_g[(size_t)bh * SEQ + i0 + tid] = inv;
    }
    __syncthreads();

    const int g = lane >> 2;
    #pragma unroll
    for (int i = 0; i < 2; ++i) {
        const float ivlo = psum[wm + i * 16 + g];
        const float ivhi = psum[wm + i * 16 + 8 + g];
        #pragma unroll
        for (int j = 0; j < 2; ++j)
            store_acc_half(g_ctx + (size_t)(b * SEQ + i0 + wm + i * 16) * DM
                               + h * DEPTH + cn + j * 16,
                           cacc[i][j].x, DM, lane, ivlo, ivhi);
    }
}

// ---------------------------------------------------------------------------
// Pass B: scores replay, cp.async double-buffered K, j-split across 2 blocks.
// blockIdx.x: bit0 = j-half (8 tiles each), rest = i-tile.
// attn = __expf(S) * rowinv written ONCE, fp32 streaming stores.
// Dynamic smem: Qs[128*72] | Ks[2][128*72] halves | invs[128] floats
// ---------------------------------------------------------------------------
#define AW_Q   0
#define AW_K(s) (9216 + (s) * 9216)
#define AW_SMEM_BYTES (27648 * 2 + 128 * 4)

__global__ __launch_bounds__(256)
void attn_write_fp16(float* __restrict__ attn, const float* __restrict__ rowinv)
{
    extern __shared__ __half smh[];
    __half* Qs = smh + AW_Q;
    float* invs = (float*)(smh + 27648);

    const int bh = blockIdx.y;
    const int b  = bh >> 4;
    const int h  = bh & 15;
    const int i0 = (blockIdx.x >> 1) * 128;
    const int jbase = (blockIdx.x & 1) * 8;   // first j-tile (of 8)
    const int tid  = threadIdx.x;
    const int lane = tid & 31;
    const int wid  = tid >> 5;
    const int wm   = (wid >> 1) * 32;
    const int wn   = (wid & 1) * 64;

    const __half* qbase = g_q + (size_t)b * SEQ * DM + h * DEPTH;
    const __half* kbase = g_k + (size_t)b * SEQ * DM + h * DEPTH;
    float* obase = attn + (size_t)bh * SEQ * SEQ;

    const int lR = tid >> 3;          // 0..31
    const int lC = (tid & 7) * 8;     // 0..56

    // Prefetch first K tile into stage 0
    #pragma unroll
    for (int p = 0; p < 4; ++p) {
        const int r = lR + p * 32;
        cp_async16(&smh[AW_K(0) + r * 72 + lC],
                   kbase + (size_t)(jbase * 128 + r) * DM + lC);
    }
    cp_commit();

    #pragma unroll
    for (int p = 0; p < 4; ++p) {
        const int r = lR + p * 32;
        *(uint4*)&Qs[r * 72 + lC] =
            *(const uint4*)(qbase + (size_t)(i0 + r) * DM + lC);
    }
    if (tid < 128) invs[tid] = rowinv[(size_t)bh * SEQ + i0 + tid];

    const int g = lane >> 2, t = lane & 3;

    for (int jj = 0; jj < 8; ++jj) {
        const int j0 = (jbase + jj) * 128;

        __syncthreads();   // all warps done reading stage (jj+1)&1
        if (jj + 1 < 8) {
            const int s = (jj + 1) & 1;
            const int jn = (jbase + jj + 1) * 128;
            #pragma unroll
            for (int p = 0; p < 4; ++p) {
                const int r = lR + p * 32;
                cp_async16(&smh[AW_K(s) + r * 72 + lC],
                           kbase + (size_t)(jn + r) * DM + lC);
            }
            cp_commit();
            cp_wait<1>();
        } else {
            cp_wait<0>();
        }
        __syncthreads();   // K(jj) visible

        const __half* Ks = smh + AW_K(jj & 1);

        wmma::fragment<wmma::accumulator, 16, 16, 16, float> sacc[2][4];
        #pragma unroll
        for (int i = 0; i < 2; ++i)
            #pragma unroll
            for (int j = 0; j < 4; ++j)
                wmma::fill_fragment(sacc[i][j], 0.0f);

        #pragma unroll
        for (int kk = 0; kk < DEPTH; kk += 16) {
            wmma::fragment<wmma::matrix_a, 16, 16, 16, __half,
                           wmma::row_major> af[2];
            wmma::fragment<wmma::matrix_b, 16, 16, 16, __half,
                           wmma::col_major> bf[4];
            #pragma unroll
            for (int i = 0; i < 2; ++i)
                wmma::load_matrix_sync(af[i], &Qs[(wm + i * 16) * 72 + kk], 72);
            #pragma unroll
            for (int j = 0; j < 4; ++j)
                wmma::load_matrix_sync(bf[j], &Ks[(wn + j * 16) * 72 + kk], 72);
            #pragma unroll
            for (int i = 0; i < 2; ++i)
                #pragma unroll
                for (int j = 0; j < 4; ++j)
                    wmma::mma_sync(sacc[i][j], af[i], bf[j], sacc[i][j]);
        }

        #pragma unroll
        for (int i = 0; i < 2; ++i) {
            const float ivlo = invs[wm + i * 16 + g];
            const float ivhi = invs[wm + i * 16 + 8 + g];
            #pragma unroll
            for (int j = 0; j < 4; ++j) {
                float* base = obase + (size_t)(i0 + wm + i * 16) * SEQ
                            + j0 + wn + j * 16;
                const float* x = sacc[i][j].x;
                float2 v;
                v.x = __expf(x[0]) * ivlo; v.y = __expf(x[1]) * ivlo;
                __stcs((float2*)(base + (size_t)g * SEQ + 2 * t), v);
                v.x = __expf(x[2]) * ivhi; v.y = __expf(x[3]) * ivhi;
                __stcs((float2*)(base + (size_t)(g + 8) * SEQ + 2 * t), v);
                v.x = __expf(x[4]) * ivlo; v.y = __expf(x[5]) * ivlo;
                __stcs((float2*)(base + (size_t)g * SEQ + 2 * t + 8), v);
                v.x = __expf(x[6]) * ivhi; v.y = __expf(x[7]) * ivhi;
                __stcs((float2*)(base + (size_t)(g + 8) * SEQ + 2 * t + 8), v);
            }
        }
    }
}

// ---------------------------------------------------------------------------
extern "C" void kernel_launch(void* const* d_in, const int* in_sizes, int n_in,
                              void* d_out, int out_size)
{
    const float* query = (const float*)d_in[0];
    const float* key   = (const float*)d_in[1];
    const float* value = (const float*)d_in[2];
    const float* Wq = (const float*)d_in[3];
    const float* bq = (const float*)d_in[4];
    const float* Wk = (const float*)d_in[5];
    const float* bk = (const float*)d_in[6];
    const float* Wv = (const float*)d_in[7];
    const float* bv = (const float*)d_in[8];
    const float* Wo = (const float*)d_in[9];
    const float* bo = (const float*)d_in[10];

    float* out  = (float*)d_out;
    float* attn = out + (size_t)BATCH * SEQ * DM;

    float* rowinv;
    cudaGetSymbolAddress((void**)&rowinv, g_rowinv);

    static int init_done = 0;
    static cudaStream_t s2;
    static cudaEvent_t ev1, ev2;
    if (!init_done) {
        cudaFuncSetAttribute(attn_fused_fp16,
                             cudaFuncAttributeMaxDynamicSharedMemorySize,
                             FS_HALVES * 2);
        cudaFuncSetAttribute(qkv_proj_fp16,
                             cudaFuncAttributeMaxDynamicSharedMemorySize,
                             GE_SMEM_BYTES);
        cudaFuncSetAttribute(o_proj_fp16,
                             cudaFuncAttributeMaxDynamicSharedMemorySize,
                             GE_SMEM_BYTES);
        cudaFuncSetAttribute(attn_write_fp16,
                             cudaFuncAttributeMaxDynamicSharedMemorySize,
                             AW_SMEM_BYTES);
        cudaStreamCreateWithFlags(&s2, cudaStreamNonBlocking);
        cudaEventCreateWithFlags(&ev1, cudaEventDisableTiming);
        cudaEventCreateWithFlags(&ev2, cudaEventDisableTiming);
        init_done = 1;
    }

    // One launch converts all 7 tensors to fp16
    dim3 gcvt(256, 1, 7);
    f2h_all<<<gcvt, 256>>>(query, key, value, Wq, Wk, Wv, Wo);

    dim3 gqkv(DM / 128, MROWS / 128, 3);   // (8, 32, 3)
    qkv_proj_fp16<<<gqkv, 256, GE_SMEM_BYTES>>>(bq, bk, bv);

    dim3 gatt(SEQ / 128, BATCH * NH);      // (16, 32)
    attn_fused_fp16<<<gatt, 256, FS_HALVES * 2>>>(rowinv);

    // Fork: attn_write (side stream) runs concurrently with o_proj (main)
    cudaEventRecord(ev1, 0);
    cudaStreamWaitEvent(s2, ev1, 0);
    dim3 gaw(SEQ / 128 * 2, BATCH * NH);   // (32, 32): j-split x2
    attn_write_fp16<<<gaw, 256, AW_SMEM_BYTES, s2>>>(attn, rowinv);

    dim3 gproj(DM / 128, MROWS / 128);     // (8, 32)
    o_proj_fp16<<<gproj, 256, GE_SMEM_BYTES>>>(bo, out);

    // Join
    cudaEventRecord(ev2, s2);
    cudaStreamWaitEvent(0, ev2, 0);
}